// round 1
// baseline (speedup 1.0000x reference)
#include <cuda_runtime.h>
#include <math.h>

#define N_NODES 8192
#define N_EDGES 4096
#define NNZ_IN  65536
#define DIN_    256
#define D_      128

#define E_CONST 2.7182818284590452f
#define EM1     1.7182818284590452f
#define INV_TEMP (1.0f/11.313708498984761f)  // 1/sqrt(128)

// ---------------- scratch (device globals; re-zeroed every launch) -------------
__device__ unsigned int g_bitmap[(size_t)N_NODES * N_EDGES / 32];  // 4 MB
__device__ int   g_kept_n[NNZ_IN];
__device__ int   g_kept_e[NNZ_IN];
__device__ int   g_kept_count;
__device__ int   g_deg_e[N_EDGES];
__device__ int   g_deg_n[N_NODES];
__device__ int   g_rowptr_e[N_EDGES + 1];
__device__ int   g_rowptr_n[N_NODES + 1];
__device__ int   g_cur_e[N_EDGES];
__device__ int   g_cur_n[N_NODES];
__device__ int   g_csr_e[NNZ_IN];   // kept-pair index, grouped by edge
__device__ int   g_csr_n[NNZ_IN];   // kept-pair index, grouped by node
__device__ float g_x4[(size_t)N_NODES * D_];
__device__ float g_xt[(size_t)N_NODES * D_];
__device__ float g_rowv[N_NODES];
__device__ float g_edge[(size_t)N_EDGES * D_];
__device__ float g_edge4[(size_t)N_EDGES * D_];
__device__ float g_Y[(size_t)N_EDGES * D_];
__device__ float g_Y2[(size_t)N_EDGES * D_];
__device__ float g_Pval[NNZ_IN];
__device__ float g_Qval[NNZ_IN];
__device__ float g_score[NNZ_IN];
__device__ float g_v[N_NODES];
__device__ float g_w[N_NODES];
__device__ float g_r[N_NODES];
__device__ float g_s[D_], g_cxt[D_], g_t[D_], g_p1[D_], g_p2[D_];
__device__ float g_alpha;

// ---------------- kernels ----------------

__global__ void k_zero() {
    int i = blockIdx.x * blockDim.x + threadIdx.x;
    int stride = gridDim.x * blockDim.x;
    for (int j = i; j < (int)(sizeof(g_bitmap)/4); j += stride) g_bitmap[j] = 0u;
    for (int j = i; j < N_EDGES; j += stride) { g_deg_e[j] = 0; g_cur_e[j] = 0; }
    for (int j = i; j < N_NODES; j += stride) { g_deg_n[j] = 0; g_cur_n[j] = 0; g_v[j] = 0.f; }
    for (int j = i; j < D_; j += stride) { g_s[j]=0.f; g_cxt[j]=0.f; g_t[j]=0.f; g_p1[j]=0.f; g_p2[j]=0.f; }
    if (i == 0) { g_kept_count = 0; g_alpha = 0.f; }
}

__global__ void k_dedup(const int* __restrict__ nodes, const int* __restrict__ edges) {
    int i = blockIdx.x * blockDim.x + threadIdx.x;
    if (i >= NNZ_IN) return;
    int n = nodes[i], e = edges[i];
    size_t bit = (size_t)e * N_NODES + (size_t)n;
    unsigned int mask = 1u << (bit & 31);
    unsigned int old = atomicOr(&g_bitmap[bit >> 5], mask);
    if (!(old & mask)) {
        int k = atomicAdd(&g_kept_count, 1);
        g_kept_n[k] = n; g_kept_e[k] = e;
        atomicAdd(&g_deg_e[e], 1);
        atomicAdd(&g_deg_n[n], 1);
    }
}

// exclusive scan of counts -> rowptr; which==0: edges (L=4096), which==1: nodes (L=8192)
__global__ void k_scan(int which) {
    __shared__ int sh[1024];
    const int* cnt = which ? g_deg_n : g_deg_e;
    int* rp        = which ? g_rowptr_n : g_rowptr_e;
    int L          = which ? N_NODES : N_EDGES;
    int tid = threadIdx.x;
    int C = L / 1024;
    int base = tid * C;
    int s = 0;
    for (int j = 0; j < C; j++) s += cnt[base + j];
    sh[tid] = s; __syncthreads();
    for (int off = 1; off < 1024; off <<= 1) {
        int v = (tid >= off) ? sh[tid - off] : 0;
        __syncthreads();
        sh[tid] += v;
        __syncthreads();
    }
    int run = (tid == 0) ? 0 : sh[tid - 1];
    for (int j = 0; j < C; j++) { rp[base + j] = run; run += cnt[base + j]; }
    if (tid == 1023) rp[L] = run;
}

__global__ void k_fill() {
    int i = blockIdx.x * blockDim.x + threadIdx.x;
    if (i >= g_kept_count) return;
    int n = g_kept_n[i], e = g_kept_e[i];
    int pe = g_rowptr_e[e] + atomicAdd(&g_cur_e[e], 1);
    g_csr_e[pe] = i;
    int pn = g_rowptr_n[n] + atomicAdd(&g_cur_n[n], 1);
    g_csr_n[pn] = i;
}

// x4 = x@W2 ; xt = x@W + b     (8192x256 * 256x128, shared x tiles)
__global__ void k_gemm_x(const float* __restrict__ x, const float* __restrict__ W,
                         const float* __restrict__ W2, const float* __restrict__ bias) {
    const int ROWS = 16, KC = 64;
    __shared__ float xs[ROWS][KC];
    int d  = threadIdx.x;           // 0..127
    int r0 = blockIdx.x * ROWS;
    float acc1[ROWS], acc2[ROWS];
#pragma unroll
    for (int r = 0; r < ROWS; r++) { acc1[r] = 0.f; acc2[r] = 0.f; }
    for (int k0 = 0; k0 < DIN_; k0 += KC) {
        for (int t = threadIdx.x; t < ROWS * KC; t += 128) {
            int rr = t / KC, cc = t % KC;
            xs[rr][cc] = x[(size_t)(r0 + rr) * DIN_ + k0 + cc];
        }
        __syncthreads();
        for (int kk = 0; kk < KC; kk++) {
            float wv  = W[(size_t)(k0 + kk) * D_ + d];
            float w2v = W2[(size_t)(k0 + kk) * D_ + d];
#pragma unroll
            for (int r = 0; r < ROWS; r++) {
                float xv = xs[r][kk];
                acc1[r] = fmaf(xv, wv,  acc1[r]);
                acc2[r] = fmaf(xv, w2v, acc2[r]);
            }
        }
        __syncthreads();
    }
    float b = bias[d];
#pragma unroll
    for (int r = 0; r < ROWS; r++) {
        g_xt[(size_t)(r0 + r) * D_ + d] = acc1[r] + b;
        g_x4[(size_t)(r0 + r) * D_ + d] = acc2[r];
    }
}

// row[n] = dot(q_ctx, x4[n]) / TEMP   (one warp per node)
__global__ void k_row(const float* __restrict__ q_ctx) {
    int n = blockIdx.x * (blockDim.x / 32) + (threadIdx.x >> 5);
    int lane = threadIdx.x & 31;
    if (n >= N_NODES) return;
    float s = 0.f;
    for (int d = lane; d < D_; d += 32) s += g_x4[(size_t)n * D_ + d] * q_ctx[d];
#pragma unroll
    for (int o = 16; o; o >>= 1) s += __shfl_xor_sync(0xffffffffu, s, o);
    if (lane == 0) g_rowv[n] = s * INV_TEMP;
}

// column sums of x4 and xt
__global__ void k_colsum() {
    int d = threadIdx.x;
    int r0 = blockIdx.x * 128;
    float s4 = 0.f, st = 0.f;
    for (int r = 0; r < 128; r++) {
        s4 += g_x4[(size_t)(r0 + r) * D_ + d];
        st += g_xt[(size_t)(r0 + r) * D_ + d];
    }
    atomicAdd(&g_s[d], s4);
    atomicAdd(&g_cxt[d], st);
}

// per edge: softmax over support, Pval, u, alpha, v, edge_out, Y
__global__ void k_edge() {
    int e = blockIdx.x;
    int beg = g_rowptr_e[e], end = g_rowptr_e[e + 1];
    int deg = end - beg;
    float c = 1.0f / ((float)N_NODES + (float)deg * EM1);
    float u = c + (deg == 0 ? (1.0f / N_NODES) : 0.0f);
    __shared__ float red[128];
    int tid = threadIdx.x;

    float m = -INFINITY;
    for (int j = beg + tid; j < end; j += 128) {
        int k = g_csr_e[j];
        m = fmaxf(m, g_rowv[g_kept_n[k]]);
    }
    red[tid] = m; __syncthreads();
    for (int o = 64; o; o >>= 1) { if (tid < o) red[tid] = fmaxf(red[tid], red[tid + o]); __syncthreads(); }
    m = red[0]; __syncthreads();

    float z = 0.f;
    for (int j = beg + tid; j < end; j += 128) {
        int k = g_csr_e[j];
        z += expf(g_rowv[g_kept_n[k]] - m);
    }
    red[tid] = z; __syncthreads();
    for (int o = 64; o; o >>= 1) { if (tid < o) red[tid] += red[tid + o]; __syncthreads(); }
    z = red[0];
    float invz = (deg > 0) ? (1.0f / z) : 0.f;

    for (int j = beg + tid; j < end; j += 128) {
        int k = g_csr_e[j];
        int n = g_kept_n[k];
        float p = EM1 * c + expf(g_rowv[n] - m) * invz;
        g_Pval[k] = p;
        atomicAdd(&g_v[n], u * p);
    }
    if (tid == 0) atomicAdd(&g_alpha, u * u);
    __syncthreads();   // make g_Pval visible inside block

    int d = tid;
    float acc = 0.f, accy = 0.f;
    for (int j = beg; j < end; j++) {
        int k = g_csr_e[j];
        int n = g_kept_n[k];
        float p = g_Pval[k];
        acc  = fmaf(p, g_xt[(size_t)n * D_ + d], acc);
        accy = fmaf(p, g_x4[(size_t)n * D_ + d], accy);
    }
    g_edge[(size_t)e * D_ + d] = u * g_cxt[d] + acc;
    g_Y[(size_t)e * D_ + d]    = accy;
}

// edge4 = edge @ W3   (4096x128 * 128x128)
__global__ void k_gemm_e4(const float* __restrict__ W3) {
    const int ROWS = 16, KC = 64;
    __shared__ float xs[ROWS][KC];
    int d  = threadIdx.x;
    int r0 = blockIdx.x * ROWS;
    float acc[ROWS];
#pragma unroll
    for (int r = 0; r < ROWS; r++) acc[r] = 0.f;
    for (int k0 = 0; k0 < D_; k0 += KC) {
        for (int t = threadIdx.x; t < ROWS * KC; t += 128) {
            int rr = t / KC, cc = t % KC;
            xs[rr][cc] = g_edge[(size_t)(r0 + rr) * D_ + k0 + cc];
        }
        __syncthreads();
        for (int kk = 0; kk < KC; kk++) {
            float wv = W3[(size_t)(k0 + kk) * D_ + d];
#pragma unroll
            for (int r = 0; r < ROWS; r++) acc[r] = fmaf(xs[r][kk], wv, acc[r]);
        }
        __syncthreads();
    }
#pragma unroll
    for (int r = 0; r < ROWS; r++) g_edge4[(size_t)(r0 + r) * D_ + d] = acc[r];
}

// per-nonzero score: dot(x4[n], edge4[e]) / TEMP (one warp per nnz)
__global__ void k_score() {
    int k = blockIdx.x * (blockDim.x / 32) + (threadIdx.x >> 5);
    int lane = threadIdx.x & 31;
    if (k >= g_kept_count) return;
    int n = g_kept_n[k], e = g_kept_e[k];
    float s = 0.f;
    for (int d = lane; d < D_; d += 32)
        s += g_x4[(size_t)n * D_ + d] * g_edge4[(size_t)e * D_ + d];
#pragma unroll
    for (int o = 16; o; o >>= 1) s += __shfl_xor_sync(0xffffffffu, s, o);
    if (lane == 0) g_score[k] = s * INV_TEMP;
}

// per node: softmax over its edges -> Qval, w, r  (one warp per node)
__global__ void k_node2() {
    int n = blockIdx.x * (blockDim.x / 32) + (threadIdx.x >> 5);
    int lane = threadIdx.x & 31;
    if (n >= N_NODES) return;
    int beg = g_rowptr_n[n], end = g_rowptr_n[n + 1];
    int dn = end - beg;
    float g = 1.0f / ((float)N_EDGES + (float)dn * EM1);
    float w = g + (dn == 0 ? (1.0f / N_EDGES) : 0.0f);

    float m = -INFINITY;
    for (int j = beg + lane; j < end; j += 32) m = fmaxf(m, g_score[g_csr_n[j]]);
#pragma unroll
    for (int o = 16; o; o >>= 1) m = fmaxf(m, __shfl_xor_sync(0xffffffffu, m, o));
    float z = 0.f;
    for (int j = beg + lane; j < end; j += 32) z += expf(g_score[g_csr_n[j]] - m);
#pragma unroll
    for (int o = 16; o; o >>= 1) z += __shfl_xor_sync(0xffffffffu, z, o);
    float invz = (dn > 0) ? (1.0f / z) : 0.f;
    for (int j = beg + lane; j < end; j += 32) {
        int k = g_csr_n[j];
        g_Qval[k] = EM1 * g + expf(g_score[k] - m) * invz;
    }
    if (lane == 0) {
        g_w[n] = w;
        g_r[n] = (dn > 0) ? ((float)dn * EM1 * g + 1.0f) : 0.0f;
    }
}

// Y2[e,:] = sum_k Qval[k] * x4[n_k,:]
__global__ void k_y2() {
    int e = blockIdx.x, d = threadIdx.x;
    int beg = g_rowptr_e[e], end = g_rowptr_e[e + 1];
    float acc = 0.f;
    for (int j = beg; j < end; j++) {
        int k = g_csr_e[j];
        acc = fmaf(g_Qval[k], g_x4[(size_t)g_kept_n[k] * D_ + d], acc);
    }
    g_Y2[(size_t)e * D_ + d] = acc;
}

// t = sum v_n x4[n]; p1 = sum w_n x4[n]; p2 = sum r_n x4[n]
__global__ void k_reduce2() {
    int d = threadIdx.x;
    int r0 = blockIdx.x * 128;
    float t = 0.f, p1 = 0.f, p2 = 0.f;
    for (int r = 0; r < 128; r++) {
        int n = r0 + r;
        float x = g_x4[(size_t)n * D_ + d];
        t  = fmaf(g_v[n], x, t);
        p1 = fmaf(g_w[n], x, p1);
        p2 = fmaf(g_r[n], x, p2);
    }
    atomicAdd(&g_t[d], t);
    atomicAdd(&g_p1[d], p1);
    atomicAdd(&g_p2[d], p2);
}

// out[n,:] = elu( (alpha+v_n)*s + t + (E*w_n + r_n)*p1 + w_n*p2 + P^T Y + Q Y2 )
__global__ void k_final(float* __restrict__ out) {
    int n = blockIdx.x, d = threadIdx.x;
    int beg = g_rowptr_n[n], end = g_rowptr_n[n + 1];
    float z1 = 0.f, z2 = 0.f;
    for (int j = beg; j < end; j++) {
        int k = g_csr_n[j];
        int e = g_kept_e[k];
        z1 = fmaf(g_Pval[k], g_Y[(size_t)e * D_ + d],  z1);
        z2 = fmaf(g_Qval[k], g_Y2[(size_t)e * D_ + d], z2);
    }
    float val = (g_alpha + g_v[n]) * g_s[d] + g_t[d]
              + ((float)N_EDGES * g_w[n] + g_r[n]) * g_p1[d]
              + g_w[n] * g_p2[d] + z1 + z2;
    out[(size_t)n * D_ + d] = (val > 0.f) ? val : expm1f(val);
}

// ---------------- launch ----------------
extern "C" void kernel_launch(void* const* d_in, const int* in_sizes, int n_in,
                              void* d_out, int out_size) {
    const float* x      = (const float*)d_in[0];
    const float* W      = (const float*)d_in[1];
    const float* W2     = (const float*)d_in[2];
    const float* W3     = (const float*)d_in[3];
    const float* bias   = (const float*)d_in[4];
    const float* q_ctx  = (const float*)d_in[5];
    const int*   hidx   = (const int*)d_in[6];   // [2, NNZ]: nodes then edges
    const int* nodes = hidx;
    const int* edges = hidx + NNZ_IN;
    float* out = (float*)d_out;

    k_zero<<<2048, 512>>>();
    k_dedup<<<NNZ_IN / 256, 256>>>(nodes, edges);
    k_scan<<<1, 1024>>>(0);
    k_scan<<<1, 1024>>>(1);
    k_fill<<<NNZ_IN / 256, 256>>>();
    k_gemm_x<<<N_NODES / 16, 128>>>(x, W, W2, bias);
    k_row<<<N_NODES / 8, 256>>>(q_ctx);
    k_colsum<<<N_NODES / 128, 128>>>();
    k_edge<<<N_EDGES, 128>>>();
    k_gemm_e4<<<N_EDGES / 16, 128>>>(W3);
    k_score<<<NNZ_IN / 8, 256>>>();
    k_node2<<<N_NODES / 8, 256>>>();
    k_y2<<<N_EDGES, 128>>>();
    k_reduce2<<<N_NODES / 128, 128>>>();
    k_final<<<N_NODES, 128>>>(out);
}

// round 2
// speedup vs baseline: 1.2933x; 1.2933x over previous
#include <cuda_runtime.h>
#include <math.h>

#define N_NODES 8192
#define N_EDGES 4096
#define NNZ_IN  65536
#define DIN_    256
#define D_      128

#define EM1     1.7182818284590452f
#define INV_TEMP (1.0f/11.313708498984761f)  // 1/sqrt(128)

// ---------------- scratch (device globals) ----------------
__device__ unsigned int g_bitmap[(size_t)N_NODES * N_EDGES / 32];  // 4 MB
__device__ int   g_kept_n[NNZ_IN];
__device__ int   g_kept_e[NNZ_IN];
__device__ int   g_kept_count;
__device__ int   g_deg_e[N_EDGES];
__device__ int   g_deg_n[N_NODES];
__device__ int   g_rowptr_e[N_EDGES + 1];
__device__ int   g_rowptr_n[N_NODES + 1];
__device__ int   g_cur_e[N_EDGES];
__device__ int   g_cur_n[N_NODES];
__device__ int   g_csr_e[NNZ_IN];
__device__ int   g_csr_n[NNZ_IN];
__device__ float g_x4[(size_t)N_NODES * D_];
__device__ float g_xt[(size_t)N_NODES * D_];
__device__ float g_rowv[N_NODES];
__device__ float g_edge[(size_t)N_EDGES * D_];
__device__ float g_edge4[(size_t)N_EDGES * D_];
__device__ float g_Y[(size_t)N_EDGES * D_];
__device__ float g_Y2[(size_t)N_EDGES * D_];
__device__ float g_Pval[NNZ_IN];
__device__ float g_Qval[NNZ_IN];
__device__ float g_score[NNZ_IN];
__device__ float g_v[N_NODES];
__device__ float g_w[N_NODES];
__device__ float g_r[N_NODES];
__device__ float g_s[D_], g_cxt[D_], g_t[D_], g_p1[D_], g_p2[D_];
__device__ float g_alpha;

// ---------------- f32x2 helpers ----------------
__device__ __forceinline__ void ffma2(unsigned long long &acc,
                                      unsigned long long a, unsigned long long b) {
    asm("fma.rn.f32x2 %0, %1, %2, %0;" : "+l"(acc) : "l"(a), "l"(b));
}
__device__ __forceinline__ unsigned long long pack2(float v) {
    unsigned long long r;
    asm("mov.b64 %0, {%1, %1};" : "=l"(r) : "f"(v));
    return r;
}
__device__ __forceinline__ void unpack2(unsigned long long a, float &lo, float &hi) {
    asm("mov.b64 {%0, %1}, %2;" : "=f"(lo), "=f"(hi) : "l"(a));
}

// ---------------- kernels ----------------

__global__ void k_zero() {
    int i = blockIdx.x * blockDim.x + threadIdx.x;
    int stride = gridDim.x * blockDim.x;
    for (int j = i; j < (int)(sizeof(g_bitmap)/4); j += stride) g_bitmap[j] = 0u;
    for (int j = i; j < N_EDGES; j += stride) { g_deg_e[j] = 0; g_cur_e[j] = 0; }
    for (int j = i; j < N_NODES; j += stride) { g_deg_n[j] = 0; g_cur_n[j] = 0; g_v[j] = 0.f; }
    for (int j = i; j < D_; j += stride) { g_s[j]=0.f; g_cxt[j]=0.f; g_t[j]=0.f; g_p1[j]=0.f; g_p2[j]=0.f; }
    if (i == 0) { g_kept_count = 0; g_alpha = 0.f; }
}

__global__ void k_dedup(const int* __restrict__ nodes, const int* __restrict__ edges) {
    int i = blockIdx.x * blockDim.x + threadIdx.x;
    if (i >= NNZ_IN) return;
    int n = nodes[i], e = edges[i];
    size_t bit = (size_t)e * N_NODES + (size_t)n;
    unsigned int mask = 1u << (bit & 31);
    unsigned int old = atomicOr(&g_bitmap[bit >> 5], mask);
    if (!(old & mask)) {
        int k = atomicAdd(&g_kept_count, 1);
        g_kept_n[k] = n; g_kept_e[k] = e;
        atomicAdd(&g_deg_e[e], 1);
        atomicAdd(&g_deg_n[n], 1);
    }
}

// both exclusive scans in one launch, warp-shuffle based. blockIdx 0: edges, 1: nodes
__global__ void k_scan2() {
    int which = blockIdx.x;
    const int* cnt = which ? g_deg_n : g_deg_e;
    int* rp        = which ? g_rowptr_n : g_rowptr_e;
    int L          = which ? N_NODES : N_EDGES;
    int tid = threadIdx.x, lane = tid & 31, wid = tid >> 5;
    int C = L >> 10;                    // 4 or 8
    int base = tid * C;
    int loc[8];
    int s = 0;
    for (int j = 0; j < C; j++) { loc[j] = cnt[base + j]; s += loc[j]; }
    int ss = s;
#pragma unroll
    for (int o = 1; o < 32; o <<= 1) { int v = __shfl_up_sync(0xffffffffu, ss, o); if (lane >= o) ss += v; }
    __shared__ int wsum[32];
    if (lane == 31) wsum[wid] = ss;
    __syncthreads();
    if (wid == 0) {
        int v = wsum[lane];
#pragma unroll
        for (int o = 1; o < 32; o <<= 1) { int u = __shfl_up_sync(0xffffffffu, v, o); if (lane >= o) v += u; }
        wsum[lane] = v;
    }
    __syncthreads();
    int run = ss - s + (wid ? wsum[wid - 1] : 0);
    for (int j = 0; j < C; j++) { rp[base + j] = run; run += loc[j]; }
    if (tid == 1023) rp[L] = run;
}

__global__ void k_fill() {
    int i = blockIdx.x * blockDim.x + threadIdx.x;
    if (i >= g_kept_count) return;
    int n = g_kept_n[i], e = g_kept_e[i];
    int pe = g_rowptr_e[e] + atomicAdd(&g_cur_e[e], 1);
    g_csr_e[pe] = i;
    int pn = g_rowptr_n[n] + atomicAdd(&g_cur_n[n], 1);
    g_csr_n[pn] = i;
}

// x4 = x@W2 ; xt = x@W + b ; plus fused rowv = (x4 . q_ctx)/TEMP and column sums
__global__ void __launch_bounds__(128) k_gemm_x(const float* __restrict__ x,
                                                const float* __restrict__ W,
                                                const float* __restrict__ W2,
                                                const float* __restrict__ bias,
                                                const float* __restrict__ q_ctx) {
    const int ROWS = 32, KC = 32;
    __shared__ __align__(8) float xs[KC][ROWS + 2];    // stride 34 (even) for 8B alignment
    __shared__ float rvs[ROWS];
    int d  = threadIdx.x;
    int r0 = blockIdx.x * ROWS;
    unsigned long long a1[ROWS/2], a2[ROWS/2];
#pragma unroll
    for (int i = 0; i < ROWS/2; i++) { a1[i] = 0ull; a2[i] = 0ull; }

    for (int k0 = 0; k0 < DIN_; k0 += KC) {
#pragma unroll
        for (int t = d; t < ROWS * KC; t += 128) {
            int rr = t >> 5, cc = t & 31;
            xs[cc][rr] = x[(size_t)(r0 + rr) * DIN_ + k0 + cc];
        }
        __syncthreads();
#pragma unroll
        for (int kk = 0; kk < KC; kk++) {
            unsigned long long wp  = pack2(W [(size_t)(k0 + kk) * D_ + d]);
            unsigned long long w2p = pack2(W2[(size_t)(k0 + kk) * D_ + d]);
            const unsigned long long* xp = (const unsigned long long*)&xs[kk][0];
#pragma unroll
            for (int r = 0; r < ROWS/2; r++) {
                unsigned long long xv = xp[r];
                ffma2(a1[r], xv, wp);
                ffma2(a2[r], xv, w2p);
            }
        }
        __syncthreads();
    }

    if (d < ROWS) rvs[d] = 0.f;
    __syncthreads();

    float b = bias[d], q = q_ctx[d];
    float c4 = 0.f, ct = 0.f;
    int lane = d & 31;
#pragma unroll
    for (int r = 0; r < ROWS/2; r++) {
        float t0, t1, f0, f1;
        unpack2(a1[r], t0, t1);
        unpack2(a2[r], f0, f1);
        t0 += b; t1 += b;
        g_xt[(size_t)(r0 + 2*r    ) * D_ + d] = t0;
        g_xt[(size_t)(r0 + 2*r + 1) * D_ + d] = t1;
        g_x4[(size_t)(r0 + 2*r    ) * D_ + d] = f0;
        g_x4[(size_t)(r0 + 2*r + 1) * D_ + d] = f1;
        ct += t0 + t1;
        c4 += f0 + f1;
        // rowv partials: reduce f0*q, f1*q over the 128 threads
        float p0 = f0 * q, p1 = f1 * q;
#pragma unroll
        for (int o = 16; o; o >>= 1) {
            p0 += __shfl_xor_sync(0xffffffffu, p0, o);
            p1 += __shfl_xor_sync(0xffffffffu, p1, o);
        }
        if (lane == 0) {
            atomicAdd(&rvs[2*r],     p0);
            atomicAdd(&rvs[2*r + 1], p1);
        }
    }
    atomicAdd(&g_s[d],   c4);
    atomicAdd(&g_cxt[d], ct);
    __syncthreads();
    if (d < ROWS) g_rowv[r0 + d] = rvs[d] * INV_TEMP;
}

// per edge: softmax over support, Pval, u, alpha, v, edge_out, Y
__global__ void k_edge() {
    int e = blockIdx.x;
    int beg = g_rowptr_e[e], end = g_rowptr_e[e + 1];
    int deg = end - beg;
    float c = 1.0f / ((float)N_NODES + (float)deg * EM1);
    float u = c + (deg == 0 ? (1.0f / N_NODES) : 0.0f);
    __shared__ float red[128];
    int tid = threadIdx.x;

    float m = -INFINITY;
    for (int j = beg + tid; j < end; j += 128) m = fmaxf(m, g_rowv[g_kept_n[g_csr_e[j]]]);
    red[tid] = m; __syncthreads();
    for (int o = 64; o; o >>= 1) { if (tid < o) red[tid] = fmaxf(red[tid], red[tid + o]); __syncthreads(); }
    m = red[0]; __syncthreads();

    float z = 0.f;
    for (int j = beg + tid; j < end; j += 128) z += expf(g_rowv[g_kept_n[g_csr_e[j]]] - m);
    red[tid] = z; __syncthreads();
    for (int o = 64; o; o >>= 1) { if (tid < o) red[tid] += red[tid + o]; __syncthreads(); }
    z = red[0];
    float invz = (deg > 0) ? (1.0f / z) : 0.f;

    for (int j = beg + tid; j < end; j += 128) {
        int k = g_csr_e[j];
        int n = g_kept_n[k];
        float p = EM1 * c + expf(g_rowv[n] - m) * invz;
        g_Pval[k] = p;
        atomicAdd(&g_v[n], u * p);
    }
    if (tid == 0) atomicAdd(&g_alpha, u * u);
    __syncthreads();

    int d = tid;
    float acc = 0.f, accy = 0.f;
    for (int j = beg; j < end; j++) {
        int k = g_csr_e[j];
        int n = g_kept_n[k];
        float p = g_Pval[k];
        acc  = fmaf(p, g_xt[(size_t)n * D_ + d], acc);
        accy = fmaf(p, g_x4[(size_t)n * D_ + d], accy);
    }
    g_edge[(size_t)e * D_ + d] = u * g_cxt[d] + acc;
    g_Y[(size_t)e * D_ + d]    = accy;
}

// edge4 = edge @ W3   (4096x128 * 128x128), f32x2 packed
__global__ void __launch_bounds__(128) k_gemm_e4(const float* __restrict__ W3) {
    const int ROWS = 32, KC = 32;
    __shared__ __align__(8) float xs[KC][ROWS + 2];
    int d  = threadIdx.x;
    int r0 = blockIdx.x * ROWS;
    unsigned long long acc[ROWS/2];
#pragma unroll
    for (int r = 0; r < ROWS/2; r++) acc[r] = 0ull;
    for (int k0 = 0; k0 < D_; k0 += KC) {
#pragma unroll
        for (int t = d; t < ROWS * KC; t += 128) {
            int rr = t >> 5, cc = t & 31;
            xs[cc][rr] = g_edge[(size_t)(r0 + rr) * D_ + k0 + cc];
        }
        __syncthreads();
#pragma unroll
        for (int kk = 0; kk < KC; kk++) {
            unsigned long long wp = pack2(W3[(size_t)(k0 + kk) * D_ + d]);
            const unsigned long long* xp = (const unsigned long long*)&xs[kk][0];
#pragma unroll
            for (int r = 0; r < ROWS/2; r++) ffma2(acc[r], xp[r], wp);
        }
        __syncthreads();
    }
#pragma unroll
    for (int r = 0; r < ROWS/2; r++) {
        float lo, hi;
        unpack2(acc[r], lo, hi);
        g_edge4[(size_t)(r0 + 2*r    ) * D_ + d] = lo;
        g_edge4[(size_t)(r0 + 2*r + 1) * D_ + d] = hi;
    }
}

// fused score + node-softmax: one warp per node, x4 row loaded once
__global__ void k_node2f() {
    int n = blockIdx.x * (blockDim.x >> 5) + (threadIdx.x >> 5);
    int lane = threadIdx.x & 31;
    if (n >= N_NODES) return;
    int beg = g_rowptr_n[n], end = g_rowptr_n[n + 1];
    int dn = end - beg;
    float g = 1.0f / ((float)N_EDGES + (float)dn * EM1);
    float w = g + (dn == 0 ? (1.0f / N_EDGES) : 0.0f);

    float x0 = g_x4[(size_t)n * D_ + lane];
    float x1 = g_x4[(size_t)n * D_ + lane + 32];
    float x2 = g_x4[(size_t)n * D_ + lane + 64];
    float x3 = g_x4[(size_t)n * D_ + lane + 96];

    float m = -INFINITY;
    for (int j = beg; j < end; j++) {
        int k = g_csr_n[j];
        const float* E4 = &g_edge4[(size_t)g_kept_e[k] * D_];
        float s = x0 * E4[lane] + x1 * E4[lane + 32] + x2 * E4[lane + 64] + x3 * E4[lane + 96];
#pragma unroll
        for (int o = 16; o; o >>= 1) s += __shfl_xor_sync(0xffffffffu, s, o);
        s *= INV_TEMP;
        if (lane == 0) g_score[k] = s;
        m = fmaxf(m, s);
    }
    float z = 0.f;
    for (int j = beg + lane; j < end; j += 32) z += expf(g_score[g_csr_n[j]] - m);
#pragma unroll
    for (int o = 16; o; o >>= 1) z += __shfl_xor_sync(0xffffffffu, z, o);
    float invz = (dn > 0) ? (1.0f / z) : 0.f;
    for (int j = beg + lane; j < end; j += 32) {
        int k = g_csr_n[j];
        g_Qval[k] = EM1 * g + expf(g_score[k] - m) * invz;
    }
    if (lane == 0) {
        g_w[n] = w;
        g_r[n] = (dn > 0) ? ((float)dn * EM1 * g + 1.0f) : 0.0f;
    }
}

// blocks [0,4096): Y2[e]=sum Qval*x4[n]; blocks [4096,4160): t/p1/p2 reductions
__global__ void k_y2r() {
    if (blockIdx.x < N_EDGES) {
        int e = blockIdx.x, d = threadIdx.x;
        int beg = g_rowptr_e[e], end = g_rowptr_e[e + 1];
        float acc = 0.f;
        for (int j = beg; j < end; j++) {
            int k = g_csr_e[j];
            acc = fmaf(g_Qval[k], g_x4[(size_t)g_kept_n[k] * D_ + d], acc);
        }
        g_Y2[(size_t)e * D_ + d] = acc;
    } else {
        int d = threadIdx.x;
        int r0 = (blockIdx.x - N_EDGES) * 128;
        float t = 0.f, p1 = 0.f, p2 = 0.f;
        for (int r = 0; r < 128; r++) {
            int n = r0 + r;
            float x = g_x4[(size_t)n * D_ + d];
            t  = fmaf(g_v[n], x, t);
            p1 = fmaf(g_w[n], x, p1);
            p2 = fmaf(g_r[n], x, p2);
        }
        atomicAdd(&g_t[d], t);
        atomicAdd(&g_p1[d], p1);
        atomicAdd(&g_p2[d], p2);
    }
}

__global__ void k_final(float* __restrict__ out) {
    int n = blockIdx.x, d = threadIdx.x;
    int beg = g_rowptr_n[n], end = g_rowptr_n[n + 1];
    float z1 = 0.f, z2 = 0.f;
    for (int j = beg; j < end; j++) {
        int k = g_csr_n[j];
        int e = g_kept_e[k];
        z1 = fmaf(g_Pval[k], g_Y[(size_t)e * D_ + d],  z1);
        z2 = fmaf(g_Qval[k], g_Y2[(size_t)e * D_ + d], z2);
    }
    float val = (g_alpha + g_v[n]) * g_s[d] + g_t[d]
              + ((float)N_EDGES * g_w[n] + g_r[n]) * g_p1[d]
              + g_w[n] * g_p2[d] + z1 + z2;
    out[(size_t)n * D_ + d] = (val > 0.f) ? val : expm1f(val);
}

// ---------------- launch ----------------
extern "C" void kernel_launch(void* const* d_in, const int* in_sizes, int n_in,
                              void* d_out, int out_size) {
    const float* x      = (const float*)d_in[0];
    const float* W      = (const float*)d_in[1];
    const float* W2     = (const float*)d_in[2];
    const float* W3     = (const float*)d_in[3];
    const float* bias   = (const float*)d_in[4];
    const float* q_ctx  = (const float*)d_in[5];
    const int*   hidx   = (const int*)d_in[6];
    const int* nodes = hidx;
    const int* edges = hidx + NNZ_IN;
    float* out = (float*)d_out;

    k_zero<<<2048, 512>>>();
    k_dedup<<<NNZ_IN / 256, 256>>>(nodes, edges);
    k_scan2<<<2, 1024>>>();
    k_fill<<<NNZ_IN / 256, 256>>>();
    k_gemm_x<<<N_NODES / 32, 128>>>(x, W, W2, bias, q_ctx);
    k_edge<<<N_EDGES, 128>>>();
    k_gemm_e4<<<N_EDGES / 32, 128>>>(W3);
    k_node2f<<<N_NODES / 8, 256>>>();
    k_y2r<<<N_EDGES + N_NODES / 128, 128>>>();
    k_final<<<N_NODES, 128>>>(out);
}

// round 3
// speedup vs baseline: 1.2960x; 1.0021x over previous
#include <cuda_runtime.h>
#include <math.h>

#define N_NODES 8192
#define N_EDGES 4096
#define NNZ_IN  65536
#define DIN_    256
#define D_      128
#define MAXDEG  512   // staging bound (avg deg 16/8; Poisson tail << 512)

#define EM1     1.7182818284590452f
#define INV_TEMP (1.0f/11.313708498984761f)  // 1/sqrt(128)

// ---------------- scratch ----------------
__device__ unsigned int g_bitmap[(size_t)N_NODES * N_EDGES / 32];  // 4 MB
__device__ int   g_kept_n[NNZ_IN];
__device__ int   g_kept_e[NNZ_IN];
__device__ int   g_kept_count;
__device__ int   g_deg_e[N_EDGES];
__device__ int   g_deg_n[N_NODES];
__device__ int   g_rowptr_e[N_EDGES + 1];
__device__ int   g_rowptr_n[N_NODES + 1];
__device__ int   g_cur_e[N_EDGES];
__device__ int   g_cur_n[N_NODES];
__device__ int   g_csr_e[NNZ_IN];
__device__ int   g_csr_n[NNZ_IN];
__device__ float g_x4[(size_t)N_NODES * D_];
__device__ float g_xt[(size_t)N_NODES * D_];
__device__ float g_rowv[N_NODES];
__device__ float g_edge[(size_t)N_EDGES * D_];
__device__ float g_edge4[(size_t)N_EDGES * D_];
__device__ float g_Y[(size_t)N_EDGES * D_];
__device__ float g_Y2[(size_t)N_EDGES * D_];
__device__ float g_Pval[NNZ_IN];
__device__ float g_Qval[NNZ_IN];
__device__ float g_score[NNZ_IN];
__device__ float g_v[N_NODES];
__device__ float g_w[N_NODES];
__device__ float g_r[N_NODES];
__device__ float g_s[D_], g_cxt[D_], g_t[D_], g_p1[D_], g_p2[D_];
__device__ float g_alpha;

// ---------------- f32x2 helpers ----------------
__device__ __forceinline__ void ffma2(unsigned long long &acc,
                                      unsigned long long a, unsigned long long b) {
    asm("fma.rn.f32x2 %0, %1, %2, %0;" : "+l"(acc) : "l"(a), "l"(b));
}
__device__ __forceinline__ unsigned long long pack2(float v) {
    unsigned long long r;
    asm("mov.b64 %0, {%1, %1};" : "=l"(r) : "f"(v));
    return r;
}
__device__ __forceinline__ void unpack2(unsigned long long a, float &lo, float &hi) {
    asm("mov.b64 {%0, %1}, %2;" : "=f"(lo), "=f"(hi) : "l"(a));
}

// ---------------- kernels ----------------

__global__ void k_zero() {
    int i = blockIdx.x * blockDim.x + threadIdx.x;
    int stride = gridDim.x * blockDim.x;
    uint4 z4 = make_uint4(0,0,0,0);
    uint4* bm = (uint4*)g_bitmap;
    for (int j = i; j < (int)(sizeof(g_bitmap)/16); j += stride) bm[j] = z4;
    for (int j = i; j < N_EDGES; j += stride) { g_deg_e[j] = 0; g_cur_e[j] = 0; }
    for (int j = i; j < N_NODES; j += stride) { g_deg_n[j] = 0; g_cur_n[j] = 0; g_v[j] = 0.f; }
    for (int j = i; j < D_; j += stride) { g_s[j]=0.f; g_cxt[j]=0.f; g_t[j]=0.f; g_p1[j]=0.f; g_p2[j]=0.f; }
    if (i == 0) { g_kept_count = 0; g_alpha = 0.f; }
}

__global__ void k_dedup(const int* __restrict__ nodes, const int* __restrict__ edges) {
    int i = blockIdx.x * blockDim.x + threadIdx.x;
    if (i >= NNZ_IN) return;
    int n = __ldg(&nodes[i]), e = __ldg(&edges[i]);
    size_t bit = (size_t)e * N_NODES + (size_t)n;
    unsigned int mask = 1u << (bit & 31);
    unsigned int old = atomicOr(&g_bitmap[bit >> 5], mask);
    if (!(old & mask)) {
        int k = atomicAdd(&g_kept_count, 1);
        g_kept_n[k] = n; g_kept_e[k] = e;
        atomicAdd(&g_deg_e[e], 1);
        atomicAdd(&g_deg_n[n], 1);
    }
}

// both exclusive scans in one launch. blockIdx 0: edges, 1: nodes
__global__ void k_scan2() {
    int which = blockIdx.x;
    const int* cnt = which ? g_deg_n : g_deg_e;
    int* rp        = which ? g_rowptr_n : g_rowptr_e;
    int L          = which ? N_NODES : N_EDGES;
    int tid = threadIdx.x, lane = tid & 31, wid = tid >> 5;
    int C = L >> 10;
    int base = tid * C;
    int loc[8];
    int s = 0;
    for (int j = 0; j < C; j++) { loc[j] = cnt[base + j]; s += loc[j]; }
    int ss = s;
#pragma unroll
    for (int o = 1; o < 32; o <<= 1) { int v = __shfl_up_sync(0xffffffffu, ss, o); if (lane >= o) ss += v; }
    __shared__ int wsum[32];
    if (lane == 31) wsum[wid] = ss;
    __syncthreads();
    if (wid == 0) {
        int v = wsum[lane];
#pragma unroll
        for (int o = 1; o < 32; o <<= 1) { int u = __shfl_up_sync(0xffffffffu, v, o); if (lane >= o) v += u; }
        wsum[lane] = v;
    }
    __syncthreads();
    int run = ss - s + (wid ? wsum[wid - 1] : 0);
    for (int j = 0; j < C; j++) { rp[base + j] = run; run += loc[j]; }
    if (tid == 1023) rp[L] = run;
}

// split: threads [0,NNZ) do edge CSR, [NNZ,2*NNZ) do node CSR — one atomic chain each
__global__ void k_fill() {
    int i = blockIdx.x * blockDim.x + threadIdx.x;
    int kc = g_kept_count;
    if (i < NNZ_IN) {
        if (i >= kc) return;
        int e = g_kept_e[i];
        int pe = g_rowptr_e[e] + atomicAdd(&g_cur_e[e], 1);
        g_csr_e[pe] = i;
    } else {
        i -= NNZ_IN;
        if (i >= kc) return;
        int n = g_kept_n[i];
        int pn = g_rowptr_n[n] + atomicAdd(&g_cur_n[n], 1);
        g_csr_n[pn] = i;
    }
}

// x4 = x@W2 ; xt = x@W + b ; fused rowv and column sums. Double-buffered smem.
__global__ void __launch_bounds__(128) k_gemm_x(const float* __restrict__ x,
                                                const float* __restrict__ W,
                                                const float* __restrict__ W2,
                                                const float* __restrict__ bias,
                                                const float* __restrict__ q_ctx) {
    const int ROWS = 32, KC = 32;
    __shared__ __align__(8) float xs[2][KC][ROWS + 2];
    __shared__ float rvs[ROWS];
    int d  = threadIdx.x;
    int r0 = blockIdx.x * ROWS;
    unsigned long long a1[ROWS/2], a2[ROWS/2];
#pragma unroll
    for (int i = 0; i < ROWS/2; i++) { a1[i] = 0ull; a2[i] = 0ull; }

    // prefetch tile 0
#pragma unroll
    for (int t = d; t < ROWS * KC; t += 128) {
        int rr = t >> 5, cc = t & 31;
        xs[0][cc][rr] = x[(size_t)(r0 + rr) * DIN_ + cc];
    }
    __syncthreads();

    for (int kt = 0; kt < DIN_ / KC; kt++) {
        int cur = kt & 1;
        // prefetch next tile into regs, store after compute barrier
        float pf[8];
        if (kt + 1 < DIN_ / KC) {
            int k0n = (kt + 1) * KC;
#pragma unroll
            for (int t = 0; t < 8; t++) {
                int idx = d + t * 128;
                int rr = idx >> 5, cc = idx & 31;
                pf[t] = x[(size_t)(r0 + rr) * DIN_ + k0n + cc];
            }
        }
        int k0 = kt * KC;
#pragma unroll
        for (int kk = 0; kk < KC; kk++) {
            unsigned long long wp  = pack2(W [(size_t)(k0 + kk) * D_ + d]);
            unsigned long long w2p = pack2(W2[(size_t)(k0 + kk) * D_ + d]);
            const unsigned long long* xp = (const unsigned long long*)&xs[cur][kk][0];
#pragma unroll
            for (int r = 0; r < ROWS/2; r++) {
                unsigned long long xv = xp[r];
                ffma2(a1[r], xv, wp);
                ffma2(a2[r], xv, w2p);
            }
        }
        if (kt + 1 < DIN_ / KC) {
            __syncthreads();
#pragma unroll
            for (int t = 0; t < 8; t++) {
                int idx = d + t * 128;
                int rr = idx >> 5, cc = idx & 31;
                xs[cur ^ 1][cc][rr] = pf[t];
            }
            __syncthreads();
        }
    }

    if (d < ROWS) rvs[d] = 0.f;
    __syncthreads();

    float b = bias[d], q = q_ctx[d];
    float c4 = 0.f, ct = 0.f;
    int lane = d & 31;
#pragma unroll
    for (int r = 0; r < ROWS/2; r++) {
        float t0, t1, f0, f1;
        unpack2(a1[r], t0, t1);
        unpack2(a2[r], f0, f1);
        t0 += b; t1 += b;
        g_xt[(size_t)(r0 + 2*r    ) * D_ + d] = t0;
        g_xt[(size_t)(r0 + 2*r + 1) * D_ + d] = t1;
        g_x4[(size_t)(r0 + 2*r    ) * D_ + d] = f0;
        g_x4[(size_t)(r0 + 2*r + 1) * D_ + d] = f1;
        ct += t0 + t1;
        c4 += f0 + f1;
        float p0 = f0 * q, p1 = f1 * q;
#pragma unroll
        for (int o = 16; o; o >>= 1) {
            p0 += __shfl_xor_sync(0xffffffffu, p0, o);
            p1 += __shfl_xor_sync(0xffffffffu, p1, o);
        }
        if (lane == 0) {
            atomicAdd(&rvs[2*r],     p0);
            atomicAdd(&rvs[2*r + 1], p1);
        }
    }
    atomicAdd(&g_s[d],   c4);
    atomicAdd(&g_cxt[d], ct);
    __syncthreads();
    if (d < ROWS) g_rowv[r0 + d] = rvs[d] * INV_TEMP;
}

// per edge: softmax, Pval, u, alpha, v, edge_out, Y. Node indices staged in smem.
__global__ void k_edge() {
    int e = blockIdx.x;
    int beg = g_rowptr_e[e], end = g_rowptr_e[e + 1];
    int deg = end - beg;
    float c = 1.0f / ((float)N_NODES + (float)deg * EM1);
    float u = c + (deg == 0 ? (1.0f / N_NODES) : 0.0f);
    __shared__ float red[128];
    __shared__ int   sk[MAXDEG];   // kept-pair index
    __shared__ int   sn[MAXDEG];   // node id
    __shared__ float sp[MAXDEG];   // Pval
    int tid = threadIdx.x;

    for (int j = tid; j < deg; j += 128) {
        int k = g_csr_e[beg + j];
        sk[j] = k;
        sn[j] = g_kept_n[k];
    }
    __syncthreads();

    float m = -INFINITY;
    for (int j = tid; j < deg; j += 128) m = fmaxf(m, g_rowv[sn[j]]);
    red[tid] = m; __syncthreads();
    for (int o = 64; o; o >>= 1) { if (tid < o) red[tid] = fmaxf(red[tid], red[tid + o]); __syncthreads(); }
    m = red[0]; __syncthreads();

    float z = 0.f;
    for (int j = tid; j < deg; j += 128) z += expf(g_rowv[sn[j]] - m);
    red[tid] = z; __syncthreads();
    for (int o = 64; o; o >>= 1) { if (tid < o) red[tid] += red[tid + o]; __syncthreads(); }
    z = red[0];
    float invz = (deg > 0) ? (1.0f / z) : 0.f;

    for (int j = tid; j < deg; j += 128) {
        int n = sn[j];
        float p = EM1 * c + expf(g_rowv[n] - m) * invz;
        sp[j] = p;
        g_Pval[sk[j]] = p;
        atomicAdd(&g_v[n], u * p);
    }
    if (tid == 0) atomicAdd(&g_alpha, u * u);
    __syncthreads();

    int d = tid;
    float acc = 0.f, accy = 0.f;
    for (int j = 0; j < deg; j++) {
        size_t row = (size_t)sn[j] * D_ + d;
        float p = sp[j];
        acc  = fmaf(p, g_xt[row], acc);
        accy = fmaf(p, g_x4[row], accy);
    }
    g_edge[(size_t)e * D_ + d] = u * g_cxt[d] + acc;
    g_Y[(size_t)e * D_ + d]    = accy;
}

// edge4 = edge @ W3
__global__ void __launch_bounds__(128) k_gemm_e4(const float* __restrict__ W3) {
    const int ROWS = 32, KC = 32;
    __shared__ __align__(8) float xs[KC][ROWS + 2];
    int d  = threadIdx.x;
    int r0 = blockIdx.x * ROWS;
    unsigned long long acc[ROWS/2];
#pragma unroll
    for (int r = 0; r < ROWS/2; r++) acc[r] = 0ull;
    for (int k0 = 0; k0 < D_; k0 += KC) {
#pragma unroll
        for (int t = d; t < ROWS * KC; t += 128) {
            int rr = t >> 5, cc = t & 31;
            xs[cc][rr] = g_edge[(size_t)(r0 + rr) * D_ + k0 + cc];
        }
        __syncthreads();
#pragma unroll
        for (int kk = 0; kk < KC; kk++) {
            unsigned long long wp = pack2(W3[(size_t)(k0 + kk) * D_ + d]);
            const unsigned long long* xp = (const unsigned long long*)&xs[kk][0];
#pragma unroll
            for (int r = 0; r < ROWS/2; r++) ffma2(acc[r], xp[r], wp);
        }
        __syncthreads();
    }
#pragma unroll
    for (int r = 0; r < ROWS/2; r++) {
        float lo, hi;
        unpack2(acc[r], lo, hi);
        g_edge4[(size_t)(r0 + 2*r    ) * D_ + d] = lo;
        g_edge4[(size_t)(r0 + 2*r + 1) * D_ + d] = hi;
    }
}

// fused score + node softmax: one warp per node
__global__ void k_node2f() {
    int n = blockIdx.x * (blockDim.x >> 5) + (threadIdx.x >> 5);
    int lane = threadIdx.x & 31;
    if (n >= N_NODES) return;
    int beg = g_rowptr_n[n], end = g_rowptr_n[n + 1];
    int dn = end - beg;
    float g = 1.0f / ((float)N_EDGES + (float)dn * EM1);
    float w = g + (dn == 0 ? (1.0f / N_EDGES) : 0.0f);

    float x0 = g_x4[(size_t)n * D_ + lane];
    float x1 = g_x4[(size_t)n * D_ + lane + 32];
    float x2 = g_x4[(size_t)n * D_ + lane + 64];
    float x3 = g_x4[(size_t)n * D_ + lane + 96];

    // stage indices for MLP
    int kreg = (lane < dn) ? g_csr_n[beg + lane] : 0;
    int ereg = (lane < dn) ? g_kept_e[kreg] : 0;

    float m = -INFINITY;
    for (int j = 0; j < dn; j++) {
        int k = __shfl_sync(0xffffffffu, kreg, j);
        int e = __shfl_sync(0xffffffffu, ereg, j);
        const float* E4 = &g_edge4[(size_t)e * D_];
        float s = x0 * E4[lane] + x1 * E4[lane + 32] + x2 * E4[lane + 64] + x3 * E4[lane + 96];
#pragma unroll
        for (int o = 16; o; o >>= 1) s += __shfl_xor_sync(0xffffffffu, s, o);
        s *= INV_TEMP;
        if (lane == 0) g_score[k] = s;
        m = fmaxf(m, s);
    }
    // dn > 32 fallback (rare): handle remaining serially
    for (int j = 32; j < dn; j++) {
        int k = g_csr_n[beg + j];
        const float* E4 = &g_edge4[(size_t)g_kept_e[k] * D_];
        float s = x0 * E4[lane] + x1 * E4[lane + 32] + x2 * E4[lane + 64] + x3 * E4[lane + 96];
#pragma unroll
        for (int o = 16; o; o >>= 1) s += __shfl_xor_sync(0xffffffffu, s, o);
        s *= INV_TEMP;
        if (lane == 0) g_score[k] = s;
        m = fmaxf(m, s);
    }
    if (dn > 32) m = -INFINITY;  // recompute max properly below for the rare big-degree case
    if (dn > 32) {
        for (int j = lane; j < dn; j += 32) m = fmaxf(m, g_score[g_csr_n[beg + j]]);
#pragma unroll
        for (int o = 16; o; o >>= 1) m = fmaxf(m, __shfl_xor_sync(0xffffffffu, m, o));
    }
    float z = 0.f;
    for (int j = lane; j < dn; j += 32) z += expf(g_score[g_csr_n[beg + j]] - m);
#pragma unroll
    for (int o = 16; o; o >>= 1) z += __shfl_xor_sync(0xffffffffu, z, o);
    float invz = (dn > 0) ? (1.0f / z) : 0.f;
    for (int j = lane; j < dn; j += 32) {
        int k = g_csr_n[beg + j];
        g_Qval[k] = EM1 * g + expf(g_score[k] - m) * invz;
    }
    if (lane == 0) {
        g_w[n] = w;
        g_r[n] = (dn > 0) ? ((float)dn * EM1 * g + 1.0f) : 0.0f;
    }
}

// blocks [0,N_EDGES): Y2; tail blocks: t/p1/p2 reductions
__global__ void k_y2r() {
    if (blockIdx.x < N_EDGES) {
        int e = blockIdx.x, d = threadIdx.x;
        int beg = g_rowptr_e[e], end = g_rowptr_e[e + 1];
        int deg = end - beg;
        __shared__ int   sn[MAXDEG];
        __shared__ float sq[MAXDEG];
        for (int j = d; j < deg; j += 128) {
            int k = g_csr_e[beg + j];
            sn[j] = g_kept_n[k];
            sq[j] = g_Qval[k];
        }
        __syncthreads();
        float acc = 0.f;
        for (int j = 0; j < deg; j++)
            acc = fmaf(sq[j], g_x4[(size_t)sn[j] * D_ + d], acc);
        g_Y2[(size_t)e * D_ + d] = acc;
    } else {
        int d = threadIdx.x;
        int r0 = (blockIdx.x - N_EDGES) * 128;
        float t = 0.f, p1 = 0.f, p2 = 0.f;
        for (int r = 0; r < 128; r++) {
            int n = r0 + r;
            float x = g_x4[(size_t)n * D_ + d];
            t  = fmaf(g_v[n], x, t);
            p1 = fmaf(g_w[n], x, p1);
            p2 = fmaf(g_r[n], x, p2);
        }
        atomicAdd(&g_t[d], t);
        atomicAdd(&g_p1[d], p1);
        atomicAdd(&g_p2[d], p2);
    }
}

__global__ void k_final(float* __restrict__ out) {
    int n = blockIdx.x, d = threadIdx.x;
    int beg = g_rowptr_n[n], end = g_rowptr_n[n + 1];
    int dn = end - beg;
    __shared__ int   se[MAXDEG];
    __shared__ float spv[MAXDEG];
    __shared__ float sqv[MAXDEG];
    for (int j = d; j < dn; j += 128) {
        int k = g_csr_n[beg + j];
        se[j]  = g_kept_e[k];
        spv[j] = g_Pval[k];
        sqv[j] = g_Qval[k];
    }
    __syncthreads();
    float z1 = 0.f, z2 = 0.f;
    for (int j = 0; j < dn; j++) {
        size_t row = (size_t)se[j] * D_ + d;
        z1 = fmaf(spv[j], g_Y[row],  z1);
        z2 = fmaf(sqv[j], g_Y2[row], z2);
    }
    float val = (g_alpha + g_v[n]) * g_s[d] + g_t[d]
              + ((float)N_EDGES * g_w[n] + g_r[n]) * g_p1[d]
              + g_w[n] * g_p2[d] + z1 + z2;
    out[(size_t)n * D_ + d] = (val > 0.f) ? val : expm1f(val);
}

// ---------------- launch ----------------
extern "C" void kernel_launch(void* const* d_in, const int* in_sizes, int n_in,
                              void* d_out, int out_size) {
    const float* x      = (const float*)d_in[0];
    const float* W      = (const float*)d_in[1];
    const float* W2     = (const float*)d_in[2];
    const float* W3     = (const float*)d_in[3];
    const float* bias   = (const float*)d_in[4];
    const float* q_ctx  = (const float*)d_in[5];
    const int*   hidx   = (const int*)d_in[6];
    const int* nodes = hidx;
    const int* edges = hidx + NNZ_IN;
    float* out = (float*)d_out;

    k_zero<<<1024, 256>>>();
    k_dedup<<<NNZ_IN / 256, 256>>>(nodes, edges);
    k_scan2<<<2, 1024>>>();
    k_gemm_x<<<N_NODES / 32, 128>>>(x, W, W2, bias, q_ctx);  // slot #4: gets profiled
    k_fill<<<2 * NNZ_IN / 256, 256>>>();
    k_edge<<<N_EDGES, 128>>>();
    k_gemm_e4<<<N_EDGES / 32, 128>>>(W3);
    k_node2f<<<N_NODES / 8, 256>>>();
    k_y2r<<<N_EDGES + N_NODES / 128, 128>>>();
    k_final<<<N_NODES, 128>>>(out);
}

// round 4
// speedup vs baseline: 1.3684x; 1.0559x over previous
#include <cuda_runtime.h>
#include <math.h>

#define N_NODES 8192
#define N_EDGES 4096
#define NNZ_IN  65536
#define DIN_    256
#define D_      128
#define MAXDEG  512

#define EM1     1.7182818284590452f
#define INV_TEMP (1.0f/11.313708498984761f)  // 1/sqrt(128)

typedef unsigned long long ull;

// ---------------- scratch ----------------
__device__ unsigned int g_bitmap[(size_t)N_NODES * N_EDGES / 32];  // 4 MB
__device__ int   g_kept_n[NNZ_IN];
__device__ int   g_kept_e[NNZ_IN];
__device__ int   g_kept_count;
__device__ int   g_deg_e[N_EDGES];
__device__ int   g_deg_n[N_NODES];
__device__ int   g_rowptr_e[N_EDGES + 1];
__device__ int   g_rowptr_n[N_NODES + 1];
__device__ int   g_cur_e[N_EDGES];
__device__ int   g_cur_n[N_NODES];
__device__ int   g_csr_e[NNZ_IN];
__device__ int   g_csr_n[NNZ_IN];
__device__ float g_x4[(size_t)N_NODES * D_];
__device__ float g_xt[(size_t)N_NODES * D_];
__device__ float g_rowv[N_NODES];
__device__ float g_edge[(size_t)N_EDGES * D_];
__device__ float g_edge4[(size_t)N_EDGES * D_];
__device__ float g_Y[(size_t)N_EDGES * D_];
__device__ float g_Y2[(size_t)N_EDGES * D_];
__device__ float g_Pval[NNZ_IN];
__device__ float g_Qval[NNZ_IN];
__device__ float g_score[NNZ_IN];
__device__ float g_v[N_NODES];
__device__ float g_w[N_NODES];
__device__ float g_r[N_NODES];
__device__ float g_s[D_], g_cxt[D_], g_t[D_], g_p1[D_], g_p2[D_];
__device__ float g_alpha;

// ---------------- f32x2 helpers ----------------
__device__ __forceinline__ void ffma2(ull &acc, ull a, ull b) {
    asm("fma.rn.f32x2 %0, %1, %2, %0;" : "+l"(acc) : "l"(a), "l"(b));
}
__device__ __forceinline__ ull pack2(float v) {
    ull r;
    asm("mov.b64 %0, {%1, %1};" : "=l"(r) : "f"(v));
    return r;
}
__device__ __forceinline__ void unpack2(ull a, float &lo, float &hi) {
    asm("mov.b64 {%0, %1}, %2;" : "=f"(lo), "=f"(hi) : "l"(a));
}

// ---------------- kernels ----------------

__global__ void k_zero() {
    int i = blockIdx.x * blockDim.x + threadIdx.x;
    int stride = gridDim.x * blockDim.x;
    uint4 z4 = make_uint4(0,0,0,0);
    uint4* bm = (uint4*)g_bitmap;
    for (int j = i; j < (int)(sizeof(g_bitmap)/16); j += stride) bm[j] = z4;
    for (int j = i; j < N_EDGES; j += stride) { g_deg_e[j] = 0; g_cur_e[j] = 0; }
    for (int j = i; j < N_NODES; j += stride) { g_deg_n[j] = 0; g_cur_n[j] = 0; g_v[j] = 0.f; }
    for (int j = i; j < D_; j += stride) { g_s[j]=0.f; g_cxt[j]=0.f; g_t[j]=0.f; g_p1[j]=0.f; g_p2[j]=0.f; }
    if (i == 0) { g_kept_count = 0; g_alpha = 0.f; }
}

__global__ void k_dedup(const int* __restrict__ nodes, const int* __restrict__ edges) {
    int i = blockIdx.x * blockDim.x + threadIdx.x;
    if (i >= NNZ_IN) return;
    int n = __ldg(&nodes[i]), e = __ldg(&edges[i]);
    size_t bit = (size_t)e * N_NODES + (size_t)n;
    unsigned int mask = 1u << (bit & 31);
    unsigned int old = atomicOr(&g_bitmap[bit >> 5], mask);
    if (!(old & mask)) {
        int k = atomicAdd(&g_kept_count, 1);
        g_kept_n[k] = n; g_kept_e[k] = e;
        atomicAdd(&g_deg_e[e], 1);
        atomicAdd(&g_deg_n[n], 1);
    }
}

__global__ void k_scan2() {
    int which = blockIdx.x;
    const int* cnt = which ? g_deg_n : g_deg_e;
    int* rp        = which ? g_rowptr_n : g_rowptr_e;
    int L          = which ? N_NODES : N_EDGES;
    int tid = threadIdx.x, lane = tid & 31, wid = tid >> 5;
    int C = L >> 10;
    int base = tid * C;
    int loc[8];
    int s = 0;
    for (int j = 0; j < C; j++) { loc[j] = cnt[base + j]; s += loc[j]; }
    int ss = s;
#pragma unroll
    for (int o = 1; o < 32; o <<= 1) { int v = __shfl_up_sync(0xffffffffu, ss, o); if (lane >= o) ss += v; }
    __shared__ int wsum[32];
    if (lane == 31) wsum[wid] = ss;
    __syncthreads();
    if (wid == 0) {
        int v = wsum[lane];
#pragma unroll
        for (int o = 1; o < 32; o <<= 1) { int u = __shfl_up_sync(0xffffffffu, v, o); if (lane >= o) v += u; }
        wsum[lane] = v;
    }
    __syncthreads();
    int run = ss - s + (wid ? wsum[wid - 1] : 0);
    for (int j = 0; j < C; j++) { rp[base + j] = run; run += loc[j]; }
    if (tid == 1023) rp[L] = run;
}

// x4 = x@W2 ; xt = x@W + b ; fused rowv + colsums.
// 256 threads: group 0 (warps 0-3) rows 0-15, group 1 (warps 4-7) rows 16-31.
__global__ void __launch_bounds__(256) k_gemm_x(const float* __restrict__ x,
                                                const float* __restrict__ W,
                                                const float* __restrict__ W2,
                                                const float* __restrict__ bias,
                                                const float* __restrict__ q_ctx) {
    const int ROWS = 32, KC = 32, HR = 16;
    __shared__ __align__(8) float xs[2][KC][ROWS + 2];
    __shared__ float rvs[ROWS];
    int tid = threadIdx.x;
    int d   = tid & 127;
    int grp = tid >> 7;
    int r0  = blockIdx.x * ROWS;
    int rbase = grp * HR;
    ull a1[HR/2], a2[HR/2];
#pragma unroll
    for (int i = 0; i < HR/2; i++) { a1[i] = 0ull; a2[i] = 0ull; }

    // prefetch tile 0 (1024 elems / 256 threads = 4 each)
#pragma unroll
    for (int t = tid; t < ROWS * KC; t += 256) {
        int rr = t >> 5, cc = t & 31;
        xs[0][cc][rr] = x[(size_t)(r0 + rr) * DIN_ + cc];
    }
    __syncthreads();

    const int NT = DIN_ / KC;  // 8
    for (int kt = 0; kt < NT; kt++) {
        int cur = kt & 1;
        float pf[4];
        if (kt + 1 < NT) {
            int k0n = (kt + 1) * KC;
#pragma unroll
            for (int t = 0; t < 4; t++) {
                int idx = tid + t * 256;
                int rr = idx >> 5, cc = idx & 31;
                pf[t] = x[(size_t)(r0 + rr) * DIN_ + k0n + cc];
            }
        }
        int k0 = kt * KC;
#pragma unroll
        for (int kk = 0; kk < KC; kk++) {
            ull wp  = pack2(W [(size_t)(k0 + kk) * D_ + d]);
            ull w2p = pack2(W2[(size_t)(k0 + kk) * D_ + d]);
            const ull* xp = (const ull*)&xs[cur][kk][rbase];
#pragma unroll
            for (int r = 0; r < HR/2; r++) {
                ull xv = xp[r];
                ffma2(a1[r], xv, wp);
                ffma2(a2[r], xv, w2p);
            }
        }
        if (kt + 1 < NT) {
            __syncthreads();
#pragma unroll
            for (int t = 0; t < 4; t++) {
                int idx = tid + t * 256;
                int rr = idx >> 5, cc = idx & 31;
                xs[cur ^ 1][cc][rr] = pf[t];
            }
            __syncthreads();
        }
    }

    if (tid < ROWS) rvs[tid] = 0.f;
    __syncthreads();

    float b = bias[d], q = q_ctx[d];
    float c4 = 0.f, ct = 0.f;
    int lane = tid & 31;
#pragma unroll
    for (int r = 0; r < HR/2; r++) {
        int row = r0 + rbase + 2*r;
        float t0, t1, f0, f1;
        unpack2(a1[r], t0, t1);
        unpack2(a2[r], f0, f1);
        t0 += b; t1 += b;
        g_xt[(size_t)(row    ) * D_ + d] = t0;
        g_xt[(size_t)(row + 1) * D_ + d] = t1;
        g_x4[(size_t)(row    ) * D_ + d] = f0;
        g_x4[(size_t)(row + 1) * D_ + d] = f1;
        ct += t0 + t1;
        c4 += f0 + f1;
        float p0 = f0 * q, p1 = f1 * q;
#pragma unroll
        for (int o = 16; o; o >>= 1) {
            p0 += __shfl_xor_sync(0xffffffffu, p0, o);
            p1 += __shfl_xor_sync(0xffffffffu, p1, o);
        }
        if (lane == 0) {
            atomicAdd(&rvs[rbase + 2*r],     p0);
            atomicAdd(&rvs[rbase + 2*r + 1], p1);
        }
    }
    atomicAdd(&g_s[d],   c4);
    atomicAdd(&g_cxt[d], ct);
    __syncthreads();
    if (tid < ROWS) g_rowv[r0 + tid] = rvs[tid] * INV_TEMP;
}

// split: threads [0,NNZ) edge CSR, [NNZ,2*NNZ) node CSR
__global__ void k_fill() {
    int i = blockIdx.x * blockDim.x + threadIdx.x;
    int kc = g_kept_count;
    if (i < NNZ_IN) {
        if (i >= kc) return;
        int e = g_kept_e[i];
        int pe = g_rowptr_e[e] + atomicAdd(&g_cur_e[e], 1);
        g_csr_e[pe] = i;
    } else {
        i -= NNZ_IN;
        if (i >= kc) return;
        int n = g_kept_n[i];
        int pn = g_rowptr_n[n] + atomicAdd(&g_cur_n[n], 1);
        g_csr_n[pn] = i;
    }
}

// per edge: softmax, Pval, u, alpha, v, edge_out, Y.
__global__ void k_edge() {
    int e = blockIdx.x;
    int beg = g_rowptr_e[e], end = g_rowptr_e[e + 1];
    int deg = end - beg;
    float c = 1.0f / ((float)N_NODES + (float)deg * EM1);
    float u = c + (deg == 0 ? (1.0f / N_NODES) : 0.0f);
    __shared__ float red[128];
    __shared__ int   sk[MAXDEG];
    __shared__ int   sn[MAXDEG];
    __shared__ float sp[MAXDEG];
    int tid = threadIdx.x;

    for (int j = tid; j < deg; j += 128) {
        int k = g_csr_e[beg + j];
        sk[j] = k;
        sn[j] = g_kept_n[k];
    }
    __syncthreads();

    float m = -INFINITY;
    for (int j = tid; j < deg; j += 128) m = fmaxf(m, g_rowv[sn[j]]);
    red[tid] = m; __syncthreads();
    for (int o = 64; o; o >>= 1) { if (tid < o) red[tid] = fmaxf(red[tid], red[tid + o]); __syncthreads(); }
    m = red[0]; __syncthreads();

    float z = 0.f;
    for (int j = tid; j < deg; j += 128) z += expf(g_rowv[sn[j]] - m);
    red[tid] = z; __syncthreads();
    for (int o = 64; o; o >>= 1) { if (tid < o) red[tid] += red[tid + o]; __syncthreads(); }
    z = red[0];
    float invz = (deg > 0) ? (1.0f / z) : 0.f;

    for (int j = tid; j < deg; j += 128) {
        int n = sn[j];
        float p = EM1 * c + expf(g_rowv[n] - m) * invz;
        sp[j] = p;
        g_Pval[sk[j]] = p;
        atomicAdd(&g_v[n], u * p);
    }
    if (tid == 0) atomicAdd(&g_alpha, u * u);
    __syncthreads();

    int d = tid;
    float acc = 0.f, accy = 0.f;
    for (int j = 0; j < deg; j++) {
        size_t row = (size_t)sn[j] * D_ + d;
        float p = sp[j];
        acc  = fmaf(p, g_xt[row], acc);
        accy = fmaf(p, g_x4[row], accy);
    }
    g_edge[(size_t)e * D_ + d] = u * g_cxt[d] + acc;
    g_Y[(size_t)e * D_ + d]    = accy;
}

// edge4 = edge @ W3 — ROWS=16, grid=256 for full-chip coverage
__global__ void __launch_bounds__(128) k_gemm_e4(const float* __restrict__ W3) {
    const int ROWS = 16, KC = 32;
    __shared__ __align__(8) float xs[KC][ROWS + 2];
    int d  = threadIdx.x;
    int r0 = blockIdx.x * ROWS;
    ull acc[ROWS/2];
#pragma unroll
    for (int r = 0; r < ROWS/2; r++) acc[r] = 0ull;
    for (int k0 = 0; k0 < D_; k0 += KC) {
#pragma unroll
        for (int t = d; t < ROWS * KC; t += 128) {
            int rr = t >> 5, cc = t & 31;
            xs[cc][rr] = g_edge[(size_t)(r0 + rr) * D_ + k0 + cc];
        }
        __syncthreads();
#pragma unroll
        for (int kk = 0; kk < KC; kk++) {
            ull wp = pack2(W3[(size_t)(k0 + kk) * D_ + d]);
            const ull* xp = (const ull*)&xs[kk][0];
#pragma unroll
            for (int r = 0; r < ROWS/2; r++) ffma2(acc[r], xp[r], wp);
        }
        __syncthreads();
    }
#pragma unroll
    for (int r = 0; r < ROWS/2; r++) {
        float lo, hi;
        unpack2(acc[r], lo, hi);
        g_edge4[(size_t)(r0 + 2*r    ) * D_ + d] = lo;
        g_edge4[(size_t)(r0 + 2*r + 1) * D_ + d] = hi;
    }
}

// fused score + node softmax: one warp per node
__global__ void k_node2f() {
    int n = blockIdx.x * (blockDim.x >> 5) + (threadIdx.x >> 5);
    int lane = threadIdx.x & 31;
    if (n >= N_NODES) return;
    int beg = g_rowptr_n[n], end = g_rowptr_n[n + 1];
    int dn = end - beg;
    float g = 1.0f / ((float)N_EDGES + (float)dn * EM1);
    float w = g + (dn == 0 ? (1.0f / N_EDGES) : 0.0f);

    float x0 = g_x4[(size_t)n * D_ + lane];
    float x1 = g_x4[(size_t)n * D_ + lane + 32];
    float x2 = g_x4[(size_t)n * D_ + lane + 64];
    float x3 = g_x4[(size_t)n * D_ + lane + 96];

    int kreg = (lane < dn) ? g_csr_n[beg + lane] : 0;
    int ereg = (lane < dn) ? g_kept_e[kreg] : 0;

    float m = -INFINITY;
    int dn32 = dn < 32 ? dn : 32;
    for (int j = 0; j < dn32; j++) {
        int k = __shfl_sync(0xffffffffu, kreg, j);
        int e = __shfl_sync(0xffffffffu, ereg, j);
        const float* E4 = &g_edge4[(size_t)e * D_];
        float s = x0 * E4[lane] + x1 * E4[lane + 32] + x2 * E4[lane + 64] + x3 * E4[lane + 96];
#pragma unroll
        for (int o = 16; o; o >>= 1) s += __shfl_xor_sync(0xffffffffu, s, o);
        s *= INV_TEMP;
        if (lane == 0) g_score[k] = s;
        m = fmaxf(m, s);
    }
    for (int j = 32; j < dn; j++) {
        int k = g_csr_n[beg + j];
        const float* E4 = &g_edge4[(size_t)g_kept_e[k] * D_];
        float s = x0 * E4[lane] + x1 * E4[lane + 32] + x2 * E4[lane + 64] + x3 * E4[lane + 96];
#pragma unroll
        for (int o = 16; o; o >>= 1) s += __shfl_xor_sync(0xffffffffu, s, o);
        s *= INV_TEMP;
        if (lane == 0) g_score[k] = s;
        m = fmaxf(m, s);
    }
    float z = 0.f;
    for (int j = lane; j < dn; j += 32) z += expf(g_score[g_csr_n[beg + j]] - m);
#pragma unroll
    for (int o = 16; o; o >>= 1) z += __shfl_xor_sync(0xffffffffu, z, o);
    float invz = (dn > 0) ? (1.0f / z) : 0.f;
    for (int j = lane; j < dn; j += 32) {
        int k = g_csr_n[beg + j];
        g_Qval[k] = EM1 * g + expf(g_score[k] - m) * invz;
    }
    if (lane == 0) {
        g_w[n] = w;
        g_r[n] = (dn > 0) ? ((float)dn * EM1 * g + 1.0f) : 0.0f;
    }
}

// blocks [0,N_EDGES): Y2; tail: t/p1/p2 reductions
__global__ void k_y2r() {
    if (blockIdx.x < N_EDGES) {
        int e = blockIdx.x, d = threadIdx.x;
        int beg = g_rowptr_e[e], end = g_rowptr_e[e + 1];
        int deg = end - beg;
        __shared__ int   sn[MAXDEG];
        __shared__ float sq[MAXDEG];
        for (int j = d; j < deg; j += 128) {
            int k = g_csr_e[beg + j];
            sn[j] = g_kept_n[k];
            sq[j] = g_Qval[k];
        }
        __syncthreads();
        float acc = 0.f;
        for (int j = 0; j < deg; j++)
            acc = fmaf(sq[j], g_x4[(size_t)sn[j] * D_ + d], acc);
        g_Y2[(size_t)e * D_ + d] = acc;
    } else {
        int d = threadIdx.x;
        int r0 = (blockIdx.x - N_EDGES) * 128;
        float t = 0.f, p1 = 0.f, p2 = 0.f;
        for (int r = 0; r < 128; r++) {
            int n = r0 + r;
            float x = g_x4[(size_t)n * D_ + d];
            t  = fmaf(g_v[n], x, t);
            p1 = fmaf(g_w[n], x, p1);
            p2 = fmaf(g_r[n], x, p2);
        }
        atomicAdd(&g_t[d], t);
        atomicAdd(&g_p1[d], p1);
        atomicAdd(&g_p2[d], p2);
    }
}

__global__ void k_final(float* __restrict__ out) {
    int n = blockIdx.x, d = threadIdx.x;
    int beg = g_rowptr_n[n], end = g_rowptr_n[n + 1];
    int dn = end - beg;
    __shared__ int   se[MAXDEG];
    __shared__ float spv[MAXDEG];
    __shared__ float sqv[MAXDEG];
    for (int j = d; j < dn; j += 128) {
        int k = g_csr_n[beg + j];
        se[j]  = g_kept_e[k];
        spv[j] = g_Pval[k];
        sqv[j] = g_Qval[k];
    }
    __syncthreads();
    float z1 = 0.f, z2 = 0.f;
    for (int j = 0; j < dn; j++) {
        size_t row = (size_t)se[j] * D_ + d;
        z1 = fmaf(spv[j], g_Y[row],  z1);
        z2 = fmaf(sqv[j], g_Y2[row], z2);
    }
    float val = (g_alpha + g_v[n]) * g_s[d] + g_t[d]
              + ((float)N_EDGES * g_w[n] + g_r[n]) * g_p1[d]
              + g_w[n] * g_p2[d] + z1 + z2;
    out[(size_t)n * D_ + d] = (val > 0.f) ? val : expm1f(val);
}

// ---------------- launch ----------------
extern "C" void kernel_launch(void* const* d_in, const int* in_sizes, int n_in,
                              void* d_out, int out_size) {
    const float* x      = (const float*)d_in[0];
    const float* W      = (const float*)d_in[1];
    const float* W2     = (const float*)d_in[2];
    const float* W3     = (const float*)d_in[3];
    const float* bias   = (const float*)d_in[4];
    const float* q_ctx  = (const float*)d_in[5];
    const int*   hidx   = (const int*)d_in[6];
    const int* nodes = hidx;
    const int* edges = hidx + NNZ_IN;
    float* out = (float*)d_out;

    k_zero<<<1024, 256>>>();
    k_dedup<<<NNZ_IN / 256, 256>>>(nodes, edges);
    k_scan2<<<2, 1024>>>();
    k_gemm_x<<<N_NODES / 32, 256>>>(x, W, W2, bias, q_ctx);  // profiled slot
    k_fill<<<2 * NNZ_IN / 256, 256>>>();
    k_edge<<<N_EDGES, 128>>>();
    k_gemm_e4<<<N_EDGES / 16, 128>>>(W3);
    k_node2f<<<N_NODES / 8, 256>>>();
    k_y2r<<<N_EDGES + N_NODES / 128, 128>>>();
    k_final<<<N_NODES, 128>>>(out);
}

// round 5
// speedup vs baseline: 1.4360x; 1.0494x over previous
#include <cuda_runtime.h>
#include <math.h>

#define N_NODES 8192
#define N_EDGES 4096
#define NNZ_IN  65536
#define DIN_    256
#define D_      128
#define MAXDEG  512

#define EM1     1.7182818284590452f
#define INV_TEMP (1.0f/11.313708498984761f)  // 1/sqrt(128)

typedef unsigned long long ull;

// ---------------- scratch ----------------
__device__ unsigned int g_bitmap[(size_t)N_NODES * N_EDGES / 32];  // 4 MB
__device__ int   g_kept_n[NNZ_IN];
__device__ int   g_kept_e[NNZ_IN];
__device__ int   g_kept_count;
__device__ int   g_deg_e[N_EDGES];
__device__ int   g_deg_n[N_NODES];
__device__ int   g_rowptr_e[N_EDGES + 1];
__device__ int   g_rowptr_n[N_NODES + 1];
__device__ int   g_cur_e[N_EDGES];
__device__ int   g_cur_n[N_NODES];
__device__ int   g_csr_e[NNZ_IN];
__device__ int   g_csr_n[NNZ_IN];
__device__ float g_x4[(size_t)N_NODES * D_];
__device__ float g_xt[(size_t)N_NODES * D_];
__device__ float g_rowv[N_NODES];
__device__ float g_edge[(size_t)N_EDGES * D_];
__device__ float g_edge4[(size_t)N_EDGES * D_];
__device__ float g_Y[(size_t)N_EDGES * D_];
__device__ float g_Y2[(size_t)N_EDGES * D_];
__device__ float g_Pval[NNZ_IN];
__device__ float g_Qval[NNZ_IN];
__device__ float g_score[NNZ_IN];
__device__ float g_v[N_NODES];
__device__ float g_w[N_NODES];
__device__ float g_r[N_NODES];
__device__ float g_s[D_], g_cxt[D_], g_t[D_], g_p1[D_], g_p2[D_];
__device__ float g_alpha;

// ---------------- f32x2 helpers ----------------
__device__ __forceinline__ void ffma2(ull &acc, ull a, ull b) {
    asm("fma.rn.f32x2 %0, %1, %2, %0;" : "+l"(acc) : "l"(a), "l"(b));
}
__device__ __forceinline__ ull pack2(float v) {
    ull r;
    asm("mov.b64 %0, {%1, %1};" : "=l"(r) : "f"(v));
    return r;
}
__device__ __forceinline__ void unpack2(ull a, float &lo, float &hi) {
    asm("mov.b64 {%0, %1}, %2;" : "=f"(lo), "=f"(hi) : "l"(a));
}

// ---------------- kernels ----------------

__global__ void k_zero() {
    int i = blockIdx.x * blockDim.x + threadIdx.x;
    int stride = gridDim.x * blockDim.x;
    uint4 z4 = make_uint4(0,0,0,0);
    uint4* bm = (uint4*)g_bitmap;
    for (int j = i; j < (int)(sizeof(g_bitmap)/16); j += stride) bm[j] = z4;
    for (int j = i; j < N_EDGES; j += stride) { g_deg_e[j] = 0; g_cur_e[j] = 0; }
    for (int j = i; j < N_NODES; j += stride) { g_deg_n[j] = 0; g_cur_n[j] = 0; g_v[j] = 0.f; }
    for (int j = i; j < D_; j += stride) { g_s[j]=0.f; g_cxt[j]=0.f; g_t[j]=0.f; g_p1[j]=0.f; g_p2[j]=0.f; }
    if (i == 0) { g_kept_count = 0; g_alpha = 0.f; }
}

__global__ void k_dedup(const int* __restrict__ nodes, const int* __restrict__ edges) {
    int i = blockIdx.x * blockDim.x + threadIdx.x;
    if (i >= NNZ_IN) return;
    int n = __ldg(&nodes[i]), e = __ldg(&edges[i]);
    size_t bit = (size_t)e * N_NODES + (size_t)n;
    unsigned int mask = 1u << (bit & 31);
    unsigned int old = atomicOr(&g_bitmap[bit >> 5], mask);
    if (!(old & mask)) {
        int k = atomicAdd(&g_kept_count, 1);
        g_kept_n[k] = n; g_kept_e[k] = e;
        atomicAdd(&g_deg_e[e], 1);
        atomicAdd(&g_deg_n[n], 1);
    }
}

__global__ void k_scan2() {
    int which = blockIdx.x;
    const int* cnt = which ? g_deg_n : g_deg_e;
    int* rp        = which ? g_rowptr_n : g_rowptr_e;
    int L          = which ? N_NODES : N_EDGES;
    int tid = threadIdx.x, lane = tid & 31, wid = tid >> 5;
    int C = L >> 10;
    int base = tid * C;
    int loc[8];
    int s = 0;
    for (int j = 0; j < C; j++) { loc[j] = cnt[base + j]; s += loc[j]; }
    int ss = s;
#pragma unroll
    for (int o = 1; o < 32; o <<= 1) { int v = __shfl_up_sync(0xffffffffu, ss, o); if (lane >= o) ss += v; }
    __shared__ int wsum[32];
    if (lane == 31) wsum[wid] = ss;
    __syncthreads();
    if (wid == 0) {
        int v = wsum[lane];
#pragma unroll
        for (int o = 1; o < 32; o <<= 1) { int u = __shfl_up_sync(0xffffffffu, v, o); if (lane >= o) v += u; }
        wsum[lane] = v;
    }
    __syncthreads();
    int run = ss - s + (wid ? wsum[wid - 1] : 0);
    for (int j = 0; j < C; j++) { rp[base + j] = run; run += loc[j]; }
    if (tid == 1023) rp[L] = run;
}

// x4 = x@W2 ; xt = x@W + b ; fused rowv + colsums.
// 256 threads, 2 row-groups of 16; smem row stride 36 floats (144B, 16B-aligned) for LDS.128.
__global__ void __launch_bounds__(256) k_gemm_x(const float* __restrict__ x,
                                                const float* __restrict__ W,
                                                const float* __restrict__ W2,
                                                const float* __restrict__ bias,
                                                const float* __restrict__ q_ctx) {
    const int ROWS = 32, KC = 32, HR = 16, STRIDE = 36;
    __shared__ __align__(16) float xs[2][KC * STRIDE];
    __shared__ float rvs[ROWS];
    int tid = threadIdx.x;
    int d   = tid & 127;
    int grp = tid >> 7;
    int r0  = blockIdx.x * ROWS;
    int rbase = grp * HR;
    ull a1[HR/2], a2[HR/2];
#pragma unroll
    for (int i = 0; i < HR/2; i++) { a1[i] = 0ull; a2[i] = 0ull; }

#pragma unroll
    for (int t = tid; t < ROWS * KC; t += 256) {
        int rr = t >> 5, cc = t & 31;
        xs[0][cc * STRIDE + rr] = x[(size_t)(r0 + rr) * DIN_ + cc];
    }
    __syncthreads();

    const int NT = DIN_ / KC;  // 8
    for (int kt = 0; kt < NT; kt++) {
        int cur = kt & 1;
        float pf[4];
        if (kt + 1 < NT) {
            int k0n = (kt + 1) * KC;
#pragma unroll
            for (int t = 0; t < 4; t++) {
                int idx = tid + t * 256;
                int rr = idx >> 5, cc = idx & 31;
                pf[t] = x[(size_t)(r0 + rr) * DIN_ + k0n + cc];
            }
        }
        int k0 = kt * KC;
#pragma unroll
        for (int kk = 0; kk < KC; kk++) {
            ull wp  = pack2(W [(size_t)(k0 + kk) * D_ + d]);
            ull w2p = pack2(W2[(size_t)(k0 + kk) * D_ + d]);
            const ulonglong2* xp = (const ulonglong2*)&xs[cur][kk * STRIDE + rbase];
#pragma unroll
            for (int rq = 0; rq < HR/4; rq++) {
                ulonglong2 xv = xp[rq];
                ffma2(a1[2*rq    ], xv.x, wp);
                ffma2(a1[2*rq + 1], xv.y, wp);
                ffma2(a2[2*rq    ], xv.x, w2p);
                ffma2(a2[2*rq + 1], xv.y, w2p);
            }
        }
        if (kt + 1 < NT) {
            __syncthreads();
#pragma unroll
            for (int t = 0; t < 4; t++) {
                int idx = tid + t * 256;
                int rr = idx >> 5, cc = idx & 31;
                xs[cur ^ 1][cc * STRIDE + rr] = pf[t];
            }
            __syncthreads();
        }
    }

    if (tid < ROWS) rvs[tid] = 0.f;
    __syncthreads();

    float b = bias[d], q = q_ctx[d];
    float c4 = 0.f, ct = 0.f;
    int lane = tid & 31;
#pragma unroll
    for (int r = 0; r < HR/2; r++) {
        int row = r0 + rbase + 2*r;
        float t0, t1, f0, f1;
        unpack2(a1[r], t0, t1);
        unpack2(a2[r], f0, f1);
        t0 += b; t1 += b;
        g_xt[(size_t)(row    ) * D_ + d] = t0;
        g_xt[(size_t)(row + 1) * D_ + d] = t1;
        g_x4[(size_t)(row    ) * D_ + d] = f0;
        g_x4[(size_t)(row + 1) * D_ + d] = f1;
        ct += t0 + t1;
        c4 += f0 + f1;
        float p0 = f0 * q, p1 = f1 * q;
#pragma unroll
        for (int o = 16; o; o >>= 1) {
            p0 += __shfl_xor_sync(0xffffffffu, p0, o);
            p1 += __shfl_xor_sync(0xffffffffu, p1, o);
        }
        if (lane == 0) {
            atomicAdd(&rvs[rbase + 2*r],     p0);
            atomicAdd(&rvs[rbase + 2*r + 1], p1);
        }
    }
    atomicAdd(&g_s[d],   c4);
    atomicAdd(&g_cxt[d], ct);
    __syncthreads();
    if (tid < ROWS) g_rowv[r0 + tid] = rvs[tid] * INV_TEMP;
}

__global__ void k_fill() {
    int i = blockIdx.x * blockDim.x + threadIdx.x;
    int kc = g_kept_count;
    if (i < NNZ_IN) {
        if (i >= kc) return;
        int e = g_kept_e[i];
        int pe = g_rowptr_e[e] + atomicAdd(&g_cur_e[e], 1);
        g_csr_e[pe] = i;
    } else {
        i -= NNZ_IN;
        if (i >= kc) return;
        int n = g_kept_n[i];
        int pn = g_rowptr_n[n] + atomicAdd(&g_cur_n[n], 1);
        g_csr_n[pn] = i;
    }
}

// per edge: softmax, Pval, u, alpha, v, edge_out, Y. Phase2: 4 warp-groups × float4.
__global__ void k_edge() {
    int e = blockIdx.x;
    int beg = g_rowptr_e[e], end = g_rowptr_e[e + 1];
    int deg = end - beg;
    float c = 1.0f / ((float)N_NODES + (float)deg * EM1);
    float u = c + (deg == 0 ? (1.0f / N_NODES) : 0.0f);
    __shared__ float red[128];
    __shared__ int   sk[MAXDEG];
    __shared__ int   sn[MAXDEG];
    __shared__ float sp[MAXDEG];
    __shared__ float sacc[4][D_];
    __shared__ float sacy[4][D_];
    int tid = threadIdx.x, lane = tid & 31, wg = tid >> 5;

    for (int j = tid; j < deg; j += 128) {
        int k = g_csr_e[beg + j];
        sk[j] = k;
        sn[j] = g_kept_n[k];
    }
    __syncthreads();

    float m = -INFINITY;
    for (int j = tid; j < deg; j += 128) m = fmaxf(m, g_rowv[sn[j]]);
    red[tid] = m; __syncthreads();
    for (int o = 64; o; o >>= 1) { if (tid < o) red[tid] = fmaxf(red[tid], red[tid + o]); __syncthreads(); }
    m = red[0]; __syncthreads();

    float z = 0.f;
    for (int j = tid; j < deg; j += 128) z += expf(g_rowv[sn[j]] - m);
    red[tid] = z; __syncthreads();
    for (int o = 64; o; o >>= 1) { if (tid < o) red[tid] += red[tid + o]; __syncthreads(); }
    z = red[0];
    float invz = (deg > 0) ? (1.0f / z) : 0.f;

    for (int j = tid; j < deg; j += 128) {
        int n = sn[j];
        float p = EM1 * c + expf(g_rowv[n] - m) * invz;
        sp[j] = p;
        g_Pval[sk[j]] = p;
        atomicAdd(&g_v[n], u * p);
    }
    if (tid == 0) atomicAdd(&g_alpha, u * u);
    __syncthreads();

    // phase 2: warp wg handles rows j = wg, wg+4, ...; lane handles float4 cols
    float4 at = make_float4(0.f,0.f,0.f,0.f);
    float4 ay = make_float4(0.f,0.f,0.f,0.f);
    for (int j = wg; j < deg; j += 4) {
        size_t roff = (size_t)sn[j] * D_;
        float4 vt = ((const float4*)&g_xt[roff])[lane];
        float4 vy = ((const float4*)&g_x4[roff])[lane];
        float p = sp[j];
        at.x = fmaf(p, vt.x, at.x); at.y = fmaf(p, vt.y, at.y);
        at.z = fmaf(p, vt.z, at.z); at.w = fmaf(p, vt.w, at.w);
        ay.x = fmaf(p, vy.x, ay.x); ay.y = fmaf(p, vy.y, ay.y);
        ay.z = fmaf(p, vy.z, ay.z); ay.w = fmaf(p, vy.w, ay.w);
    }
    ((float4*)&sacc[wg][0])[lane] = at;
    ((float4*)&sacy[wg][0])[lane] = ay;
    __syncthreads();
    int d = tid;
    float acc  = sacc[0][d] + sacc[1][d] + sacc[2][d] + sacc[3][d];
    float accy = sacy[0][d] + sacy[1][d] + sacy[2][d] + sacy[3][d];
    g_edge[(size_t)e * D_ + d] = u * g_cxt[d] + acc;
    g_Y[(size_t)e * D_ + d]    = accy;
}

// edge4 = edge @ W3 — ROWS=16, stride 20 floats (80B, 16B-aligned)
__global__ void __launch_bounds__(128) k_gemm_e4(const float* __restrict__ W3) {
    const int ROWS = 16, KC = 32, STRIDE = 20;
    __shared__ __align__(16) float xs[KC * STRIDE];
    int d  = threadIdx.x;
    int r0 = blockIdx.x * ROWS;
    ull acc[ROWS/2];
#pragma unroll
    for (int r = 0; r < ROWS/2; r++) acc[r] = 0ull;
    for (int k0 = 0; k0 < D_; k0 += KC) {
#pragma unroll
        for (int t = d; t < ROWS * KC; t += 128) {
            int rr = t >> 5, cc = t & 31;
            xs[cc * STRIDE + rr] = g_edge[(size_t)(r0 + rr) * D_ + k0 + cc];
        }
        __syncthreads();
#pragma unroll
        for (int kk = 0; kk < KC; kk++) {
            ull wp = pack2(W3[(size_t)(k0 + kk) * D_ + d]);
            const ulonglong2* xp = (const ulonglong2*)&xs[kk * STRIDE];
#pragma unroll
            for (int rq = 0; rq < ROWS/4; rq++) {
                ulonglong2 xv = xp[rq];
                ffma2(acc[2*rq    ], xv.x, wp);
                ffma2(acc[2*rq + 1], xv.y, wp);
            }
        }
        __syncthreads();
    }
#pragma unroll
    for (int r = 0; r < ROWS/2; r++) {
        float lo, hi;
        unpack2(acc[r], lo, hi);
        g_edge4[(size_t)(r0 + 2*r    ) * D_ + d] = lo;
        g_edge4[(size_t)(r0 + 2*r + 1) * D_ + d] = hi;
    }
}

// fused score + node softmax: one warp per node, float4 columns
__global__ void k_node2f() {
    int n = blockIdx.x * (blockDim.x >> 5) + (threadIdx.x >> 5);
    int lane = threadIdx.x & 31;
    if (n >= N_NODES) return;
    int beg = g_rowptr_n[n], end = g_rowptr_n[n + 1];
    int dn = end - beg;
    float g = 1.0f / ((float)N_EDGES + (float)dn * EM1);
    float w = g + (dn == 0 ? (1.0f / N_EDGES) : 0.0f);

    float4 xv = ((const float4*)&g_x4[(size_t)n * D_])[lane];

    int kreg = (lane < dn) ? g_csr_n[beg + lane] : 0;
    int ereg = (lane < dn) ? g_kept_e[kreg] : 0;

    float m = -INFINITY;
    int dn32 = dn < 32 ? dn : 32;
    for (int j = 0; j < dn32; j++) {
        int k = __shfl_sync(0xffffffffu, kreg, j);
        int e = __shfl_sync(0xffffffffu, ereg, j);
        float4 ev = ((const float4*)&g_edge4[(size_t)e * D_])[lane];
        float s = xv.x*ev.x + xv.y*ev.y + xv.z*ev.z + xv.w*ev.w;
#pragma unroll
        for (int o = 16; o; o >>= 1) s += __shfl_xor_sync(0xffffffffu, s, o);
        s *= INV_TEMP;
        if (lane == 0) g_score[k] = s;
        m = fmaxf(m, s);
    }
    for (int j = 32; j < dn; j++) {
        int k = g_csr_n[beg + j];
        float4 ev = ((const float4*)&g_edge4[(size_t)g_kept_e[k] * D_])[lane];
        float s = xv.x*ev.x + xv.y*ev.y + xv.z*ev.z + xv.w*ev.w;
#pragma unroll
        for (int o = 16; o; o >>= 1) s += __shfl_xor_sync(0xffffffffu, s, o);
        s *= INV_TEMP;
        if (lane == 0) g_score[k] = s;
        m = fmaxf(m, s);
    }
    float z = 0.f;
    for (int j = lane; j < dn; j += 32) z += expf(g_score[g_csr_n[beg + j]] - m);
#pragma unroll
    for (int o = 16; o; o >>= 1) z += __shfl_xor_sync(0xffffffffu, z, o);
    float invz = (dn > 0) ? (1.0f / z) : 0.f;
    for (int j = lane; j < dn; j += 32) {
        int k = g_csr_n[beg + j];
        g_Qval[k] = EM1 * g + expf(g_score[k] - m) * invz;
    }
    if (lane == 0) {
        g_w[n] = w;
        g_r[n] = (dn > 0) ? ((float)dn * EM1 * g + 1.0f) : 0.0f;
    }
}

// blocks [0,N_EDGES): Y2 via warp-group float4; tail: t/p1/p2 reductions
__global__ void k_y2r() {
    if (blockIdx.x < N_EDGES) {
        int e = blockIdx.x, tid = threadIdx.x, lane = tid & 31, wg = tid >> 5;
        int beg = g_rowptr_e[e], end = g_rowptr_e[e + 1];
        int deg = end - beg;
        __shared__ int   sn[MAXDEG];
        __shared__ float sq[MAXDEG];
        __shared__ float sacc[4][D_];
        for (int j = tid; j < deg; j += 128) {
            int k = g_csr_e[beg + j];
            sn[j] = g_kept_n[k];
            sq[j] = g_Qval[k];
        }
        __syncthreads();
        float4 a = make_float4(0.f,0.f,0.f,0.f);
        for (int j = wg; j < deg; j += 4) {
            float4 v = ((const float4*)&g_x4[(size_t)sn[j] * D_])[lane];
            float q = sq[j];
            a.x = fmaf(q, v.x, a.x); a.y = fmaf(q, v.y, a.y);
            a.z = fmaf(q, v.z, a.z); a.w = fmaf(q, v.w, a.w);
        }
        ((float4*)&sacc[wg][0])[lane] = a;
        __syncthreads();
        int d = tid;
        g_Y2[(size_t)e * D_ + d] = sacc[0][d] + sacc[1][d] + sacc[2][d] + sacc[3][d];
    } else {
        int d = threadIdx.x;
        int r0 = (blockIdx.x - N_EDGES) * 128;
        float t = 0.f, p1 = 0.f, p2 = 0.f;
        for (int r = 0; r < 128; r++) {
            int n = r0 + r;
            float x = g_x4[(size_t)n * D_ + d];
            t  = fmaf(g_v[n], x, t);
            p1 = fmaf(g_w[n], x, p1);
            p2 = fmaf(g_r[n], x, p2);
        }
        atomicAdd(&g_t[d], t);
        atomicAdd(&g_p1[d], p1);
        atomicAdd(&g_p2[d], p2);
    }
}

__global__ void k_final(float* __restrict__ out) {
    int n = blockIdx.x, tid = threadIdx.x, lane = tid & 31, wg = tid >> 5;
    int beg = g_rowptr_n[n], end = g_rowptr_n[n + 1];
    int dn = end - beg;
    __shared__ int   se[MAXDEG];
    __shared__ float spv[MAXDEG];
    __shared__ float sqv[MAXDEG];
    __shared__ float sz1[4][D_];
    __shared__ float sz2[4][D_];
    for (int j = tid; j < dn; j += 128) {
        int k = g_csr_n[beg + j];
        se[j]  = g_kept_e[k];
        spv[j] = g_Pval[k];
        sqv[j] = g_Qval[k];
    }
    __syncthreads();
    float4 a1 = make_float4(0.f,0.f,0.f,0.f);
    float4 a2 = make_float4(0.f,0.f,0.f,0.f);
    for (int j = wg; j < dn; j += 4) {
        size_t roff = (size_t)se[j] * D_;
        float4 v1 = ((const float4*)&g_Y [roff])[lane];
        float4 v2 = ((const float4*)&g_Y2[roff])[lane];
        float p = spv[j], q = sqv[j];
        a1.x = fmaf(p, v1.x, a1.x); a1.y = fmaf(p, v1.y, a1.y);
        a1.z = fmaf(p, v1.z, a1.z); a1.w = fmaf(p, v1.w, a1.w);
        a2.x = fmaf(q, v2.x, a2.x); a2.y = fmaf(q, v2.y, a2.y);
        a2.z = fmaf(q, v2.z, a2.z); a2.w = fmaf(q, v2.w, a2.w);
    }
    ((float4*)&sz1[wg][0])[lane] = a1;
    ((float4*)&sz2[wg][0])[lane] = a2;
    __syncthreads();
    int d = tid;
    float z1 = sz1[0][d] + sz1[1][d] + sz1[2][d] + sz1[3][d];
    float z2 = sz2[0][d] + sz2[1][d] + sz2[2][d] + sz2[3][d];
    float val = (g_alpha + g_v[n]) * g_s[d] + g_t[d]
              + ((float)N_EDGES * g_w[n] + g_r[n]) * g_p1[d]
              + g_w[n] * g_p2[d] + z1 + z2;
    out[(size_t)n * D_ + d] = (val > 0.f) ? val : expm1f(val);
}

// ---------------- launch ----------------
extern "C" void kernel_launch(void* const* d_in, const int* in_sizes, int n_in,
                              void* d_out, int out_size) {
    const float* x      = (const float*)d_in[0];
    const float* W      = (const float*)d_in[1];
    const float* W2     = (const float*)d_in[2];
    const float* W3     = (const float*)d_in[3];
    const float* bias   = (const float*)d_in[4];
    const float* q_ctx  = (const float*)d_in[5];
    const int*   hidx   = (const int*)d_in[6];
    const int* nodes = hidx;
    const int* edges = hidx + NNZ_IN;
    float* out = (float*)d_out;

    k_zero<<<1024, 256>>>();
    k_dedup<<<NNZ_IN / 256, 256>>>(nodes, edges);
    k_scan2<<<2, 1024>>>();
    k_gemm_x<<<N_NODES / 32, 256>>>(x, W, W2, bias, q_ctx);  // profiled slot
    k_fill<<<2 * NNZ_IN / 256, 256>>>();
    k_edge<<<N_EDGES, 128>>>();
    k_gemm_e4<<<N_EDGES / 16, 128>>>(W3);
    k_node2f<<<N_NODES / 8, 256>>>();
    k_y2r<<<N_EDGES + N_NODES / 128, 128>>>();
    k_final<<<N_NODES, 128>>>(out);
}

// round 6
// speedup vs baseline: 1.5540x; 1.0821x over previous
#include <cuda_runtime.h>
#include <math.h>

#define N_NODES 8192
#define N_EDGES 4096
#define NNZ_IN  65536
#define DIN_    256
#define D_      128
#define MAXDEG  512

#define EM1     1.7182818284590452f
#define INV_TEMP (1.0f/11.313708498984761f)  // 1/sqrt(128)

typedef unsigned long long ull;

// ---------------- scratch ----------------
__device__ unsigned int g_bitmap[(size_t)N_NODES * N_EDGES / 32];  // 4 MB
__device__ int   g_kept_n[NNZ_IN];
__device__ int   g_kept_e[NNZ_IN];
__device__ int   g_kept_count;
__device__ int   g_deg_e[N_EDGES];
__device__ int   g_deg_n[N_NODES];
__device__ int   g_rowptr_e[N_EDGES + 1];
__device__ int   g_rowptr_n[N_NODES + 1];
__device__ int   g_cur_e[N_EDGES];
__device__ int   g_cur_n[N_NODES];
__device__ int   g_csr_e[NNZ_IN];
__device__ int   g_csr_n[NNZ_IN];
__device__ float g_x4[(size_t)N_NODES * D_];
__device__ float g_xt[(size_t)N_NODES * D_];
__device__ float g_rowv[N_NODES];
__device__ float g_edge[(size_t)N_EDGES * D_];
__device__ float g_edge4[(size_t)N_EDGES * D_];
__device__ float g_Y[(size_t)N_EDGES * D_];
__device__ float g_Y2[(size_t)N_EDGES * D_];
__device__ float g_Pval[NNZ_IN];
__device__ float g_Qval[NNZ_IN];
__device__ float g_score[NNZ_IN];
__device__ float g_v[N_NODES];
__device__ float g_w[N_NODES];
__device__ float g_r[N_NODES];
__device__ float g_s[D_], g_cxt[D_], g_t[D_], g_p1[D_], g_p2[D_];
__device__ float g_alpha;

// ---------------- f32x2 helpers ----------------
__device__ __forceinline__ void ffma2(ull &acc, ull a, ull b) {
    asm("fma.rn.f32x2 %0, %1, %2, %0;" : "+l"(acc) : "l"(a), "l"(b));
}
__device__ __forceinline__ ull pack2(float v) {
    ull r;
    asm("mov.b64 %0, {%1, %1};" : "=l"(r) : "f"(v));
    return r;
}
__device__ __forceinline__ void unpack2(ull a, float &lo, float &hi) {
    asm("mov.b64 {%0, %1}, %2;" : "=f"(lo), "=f"(hi) : "l"(a));
}

// ---------------- kernels ----------------

__global__ void k_zero() {
    int i = blockIdx.x * blockDim.x + threadIdx.x;
    int stride = gridDim.x * blockDim.x;
    uint4 z4 = make_uint4(0,0,0,0);
    uint4* bm = (uint4*)g_bitmap;
    for (int j = i; j < (int)(sizeof(g_bitmap)/16); j += stride) bm[j] = z4;
    for (int j = i; j < N_EDGES; j += stride) { g_deg_e[j] = 0; g_cur_e[j] = 0; }
    for (int j = i; j < N_NODES; j += stride) { g_deg_n[j] = 0; g_cur_n[j] = 0; g_v[j] = 0.f; }
    for (int j = i; j < D_; j += stride) { g_s[j]=0.f; g_cxt[j]=0.f; g_t[j]=0.f; g_p1[j]=0.f; g_p2[j]=0.f; }
    if (i == 0) { g_kept_count = 0; g_alpha = 0.f; }
}

__global__ void k_dedup(const int* __restrict__ nodes, const int* __restrict__ edges) {
    int i = blockIdx.x * blockDim.x + threadIdx.x;
    if (i >= NNZ_IN) return;
    int n = __ldg(&nodes[i]), e = __ldg(&edges[i]);
    size_t bit = (size_t)e * N_NODES + (size_t)n;
    unsigned int mask = 1u << (bit & 31);
    unsigned int old = atomicOr(&g_bitmap[bit >> 5], mask);
    if (!(old & mask)) {
        int k = atomicAdd(&g_kept_count, 1);
        g_kept_n[k] = n; g_kept_e[k] = e;
        atomicAdd(&g_deg_e[e], 1);
        atomicAdd(&g_deg_n[n], 1);
    }
}

__global__ void k_scan2() {
    int which = blockIdx.x;
    const int* cnt = which ? g_deg_n : g_deg_e;
    int* rp        = which ? g_rowptr_n : g_rowptr_e;
    int L          = which ? N_NODES : N_EDGES;
    int tid = threadIdx.x, lane = tid & 31, wid = tid >> 5;
    int C = L >> 10;
    int base = tid * C;
    int loc[8];
    int s = 0;
    for (int j = 0; j < C; j++) { loc[j] = cnt[base + j]; s += loc[j]; }
    int ss = s;
#pragma unroll
    for (int o = 1; o < 32; o <<= 1) { int v = __shfl_up_sync(0xffffffffu, ss, o); if (lane >= o) ss += v; }
    __shared__ int wsum[32];
    if (lane == 31) wsum[wid] = ss;
    __syncthreads();
    if (wid == 0) {
        int v = wsum[lane];
#pragma unroll
        for (int o = 1; o < 32; o <<= 1) { int u = __shfl_up_sync(0xffffffffu, v, o); if (lane >= o) v += u; }
        wsum[lane] = v;
    }
    __syncthreads();
    int run = ss - s + (wid ? wsum[wid - 1] : 0);
    for (int j = 0; j < C; j++) { rp[base + j] = run; run += loc[j]; }
    if (tid == 1023) rp[L] = run;
}

__global__ void k_fill() {
    int i = blockIdx.x * blockDim.x + threadIdx.x;
    int kc = g_kept_count;
    if (i < NNZ_IN) {
        if (i >= kc) return;
        int e = g_kept_e[i];
        int pe = g_rowptr_e[e] + atomicAdd(&g_cur_e[e], 1);
        g_csr_e[pe] = i;
    } else {
        i -= NNZ_IN;
        if (i >= kc) return;
        int n = g_kept_n[i];
        int pn = g_rowptr_n[n] + atomicAdd(&g_cur_n[n], 1);
        g_csr_n[pn] = i;
    }
}

// x4 = x@W2 ; xt = x@W + b ; fused rowv + colsums.
// 512 threads, 4 row-groups of 8 rows over a 32-row tile.
__global__ void __launch_bounds__(512) k_gemm_x(const float* __restrict__ x,
                                                const float* __restrict__ W,
                                                const float* __restrict__ W2,
                                                const float* __restrict__ bias,
                                                const float* __restrict__ q_ctx) {
    const int ROWS = 32, KC = 32, HR = 8, STRIDE = 36;
    __shared__ __align__(16) float xs[2][KC * STRIDE];
    __shared__ float rvs[ROWS];
    int tid = threadIdx.x;
    int d   = tid & 127;
    int grp = tid >> 7;           // 0..3
    int r0  = blockIdx.x * ROWS;
    int rbase = grp * HR;         // 0,8,16,24
    ull a1[HR/2], a2[HR/2];
#pragma unroll
    for (int i = 0; i < HR/2; i++) { a1[i] = 0ull; a2[i] = 0ull; }

#pragma unroll
    for (int t = tid; t < ROWS * KC; t += 512) {
        int rr = t >> 5, cc = t & 31;
        xs[0][cc * STRIDE + rr] = x[(size_t)(r0 + rr) * DIN_ + cc];
    }
    __syncthreads();

    const int NT = DIN_ / KC;  // 8
    for (int kt = 0; kt < NT; kt++) {
        int cur = kt & 1;
        float pf[2];
        if (kt + 1 < NT) {
            int k0n = (kt + 1) * KC;
#pragma unroll
            for (int t = 0; t < 2; t++) {
                int idx = tid + t * 512;
                int rr = idx >> 5, cc = idx & 31;
                pf[t] = x[(size_t)(r0 + rr) * DIN_ + k0n + cc];
            }
        }
        int k0 = kt * KC;
#pragma unroll
        for (int kk = 0; kk < KC; kk++) {
            ull wp  = pack2(W [(size_t)(k0 + kk) * D_ + d]);
            ull w2p = pack2(W2[(size_t)(k0 + kk) * D_ + d]);
            const ulonglong2* xp = (const ulonglong2*)&xs[cur][kk * STRIDE + rbase];
#pragma unroll
            for (int rq = 0; rq < HR/4; rq++) {
                ulonglong2 xv = xp[rq];
                ffma2(a1[2*rq    ], xv.x, wp);
                ffma2(a1[2*rq + 1], xv.y, wp);
                ffma2(a2[2*rq    ], xv.x, w2p);
                ffma2(a2[2*rq + 1], xv.y, w2p);
            }
        }
        if (kt + 1 < NT) {
            __syncthreads();
#pragma unroll
            for (int t = 0; t < 2; t++) {
                int idx = tid + t * 512;
                int rr = idx >> 5, cc = idx & 31;
                xs[cur ^ 1][cc * STRIDE + rr] = pf[t];
            }
            __syncthreads();
        }
    }

    if (tid < ROWS) rvs[tid] = 0.f;
    __syncthreads();

    float b = bias[d], q = q_ctx[d];
    float c4 = 0.f, ct = 0.f;
    int lane = tid & 31;
#pragma unroll
    for (int r = 0; r < HR/2; r++) {
        int row = r0 + rbase + 2*r;
        float t0, t1, f0, f1;
        unpack2(a1[r], t0, t1);
        unpack2(a2[r], f0, f1);
        t0 += b; t1 += b;
        g_xt[(size_t)(row    ) * D_ + d] = t0;
        g_xt[(size_t)(row + 1) * D_ + d] = t1;
        g_x4[(size_t)(row    ) * D_ + d] = f0;
        g_x4[(size_t)(row + 1) * D_ + d] = f1;
        ct += t0 + t1;
        c4 += f0 + f1;
        float p0 = f0 * q, p1 = f1 * q;
#pragma unroll
        for (int o = 16; o; o >>= 1) {
            p0 += __shfl_xor_sync(0xffffffffu, p0, o);
            p1 += __shfl_xor_sync(0xffffffffu, p1, o);
        }
        if (lane == 0) {
            atomicAdd(&rvs[rbase + 2*r],     p0);
            atomicAdd(&rvs[rbase + 2*r + 1], p1);
        }
    }
    atomicAdd(&g_s[d],   c4);
    atomicAdd(&g_cxt[d], ct);
    __syncthreads();
    if (tid < ROWS) g_rowv[r0 + tid] = rvs[tid] * INV_TEMP;
}

// per edge: softmax, Pval, u, alpha, v, edge_out, Y. Phase2: 4 warp-groups × float4.
__global__ void k_edge() {
    int e = blockIdx.x;
    int beg = g_rowptr_e[e], end = g_rowptr_e[e + 1];
    int deg = end - beg;
    float c = 1.0f / ((float)N_NODES + (float)deg * EM1);
    float u = c + (deg == 0 ? (1.0f / N_NODES) : 0.0f);
    __shared__ float red[128];
    __shared__ int   sk[MAXDEG];
    __shared__ int   sn[MAXDEG];
    __shared__ float sp[MAXDEG];
    __shared__ float sacc[4][D_];
    __shared__ float sacy[4][D_];
    int tid = threadIdx.x, lane = tid & 31, wg = tid >> 5;

    for (int j = tid; j < deg; j += 128) {
        int k = g_csr_e[beg + j];
        sk[j] = k;
        sn[j] = g_kept_n[k];
    }
    __syncthreads();

    float m = -INFINITY;
    for (int j = tid; j < deg; j += 128) m = fmaxf(m, g_rowv[sn[j]]);
    red[tid] = m; __syncthreads();
    for (int o = 64; o; o >>= 1) { if (tid < o) red[tid] = fmaxf(red[tid], red[tid + o]); __syncthreads(); }
    m = red[0]; __syncthreads();

    float z = 0.f;
    for (int j = tid; j < deg; j += 128) z += expf(g_rowv[sn[j]] - m);
    red[tid] = z; __syncthreads();
    for (int o = 64; o; o >>= 1) { if (tid < o) red[tid] += red[tid + o]; __syncthreads(); }
    z = red[0];
    float invz = (deg > 0) ? (1.0f / z) : 0.f;

    for (int j = tid; j < deg; j += 128) {
        int n = sn[j];
        float p = EM1 * c + expf(g_rowv[n] - m) * invz;
        sp[j] = p;
        g_Pval[sk[j]] = p;
        atomicAdd(&g_v[n], u * p);
    }
    if (tid == 0) atomicAdd(&g_alpha, u * u);
    __syncthreads();

    float4 at = make_float4(0.f,0.f,0.f,0.f);
    float4 ay = make_float4(0.f,0.f,0.f,0.f);
    for (int j = wg; j < deg; j += 4) {
        size_t roff = (size_t)sn[j] * D_;
        float4 vt = ((const float4*)&g_xt[roff])[lane];
        float4 vy = ((const float4*)&g_x4[roff])[lane];
        float p = sp[j];
        at.x = fmaf(p, vt.x, at.x); at.y = fmaf(p, vt.y, at.y);
        at.z = fmaf(p, vt.z, at.z); at.w = fmaf(p, vt.w, at.w);
        ay.x = fmaf(p, vy.x, ay.x); ay.y = fmaf(p, vy.y, ay.y);
        ay.z = fmaf(p, vy.z, ay.z); ay.w = fmaf(p, vy.w, ay.w);
    }
    ((float4*)&sacc[wg][0])[lane] = at;
    ((float4*)&sacy[wg][0])[lane] = ay;
    __syncthreads();
    int d = tid;
    float acc  = sacc[0][d] + sacc[1][d] + sacc[2][d] + sacc[3][d];
    float accy = sacy[0][d] + sacy[1][d] + sacy[2][d] + sacy[3][d];
    g_edge[(size_t)e * D_ + d] = u * g_cxt[d] + acc;
    g_Y[(size_t)e * D_ + d]    = accy;
}

// edge4 = edge @ W3 — 256 threads, 2 row-groups of 8 over 16-row tile
__global__ void __launch_bounds__(256) k_gemm_e4(const float* __restrict__ W3) {
    const int ROWS = 16, KC = 32, HR = 8, STRIDE = 20;
    __shared__ __align__(16) float xs[KC * STRIDE];
    int tid = threadIdx.x;
    int d   = tid & 127;
    int grp = tid >> 7;
    int r0  = blockIdx.x * ROWS;
    int rbase = grp * HR;
    ull acc[HR/2];
#pragma unroll
    for (int r = 0; r < HR/2; r++) acc[r] = 0ull;
    for (int k0 = 0; k0 < D_; k0 += KC) {
#pragma unroll
        for (int t = tid; t < ROWS * KC; t += 256) {
            int rr = t >> 5, cc = t & 31;
            xs[cc * STRIDE + rr] = g_edge[(size_t)(r0 + rr) * D_ + k0 + cc];
        }
        __syncthreads();
#pragma unroll
        for (int kk = 0; kk < KC; kk++) {
            ull wp = pack2(W3[(size_t)(k0 + kk) * D_ + d]);
            const ulonglong2* xp = (const ulonglong2*)&xs[kk * STRIDE + rbase];
#pragma unroll
            for (int rq = 0; rq < HR/4; rq++) {
                ulonglong2 xv = xp[rq];
                ffma2(acc[2*rq    ], xv.x, wp);
                ffma2(acc[2*rq + 1], xv.y, wp);
            }
        }
        __syncthreads();
    }
#pragma unroll
    for (int r = 0; r < HR/2; r++) {
        float lo, hi;
        unpack2(acc[r], lo, hi);
        g_edge4[(size_t)(r0 + rbase + 2*r    ) * D_ + d] = lo;
        g_edge4[(size_t)(r0 + rbase + 2*r + 1) * D_ + d] = hi;
    }
}

// fused score + node softmax: one warp per node, float4 columns
__global__ void k_node2f() {
    int n = blockIdx.x * (blockDim.x >> 5) + (threadIdx.x >> 5);
    int lane = threadIdx.x & 31;
    if (n >= N_NODES) return;
    int beg = g_rowptr_n[n], end = g_rowptr_n[n + 1];
    int dn = end - beg;
    float g = 1.0f / ((float)N_EDGES + (float)dn * EM1);
    float w = g + (dn == 0 ? (1.0f / N_EDGES) : 0.0f);

    float4 xv = ((const float4*)&g_x4[(size_t)n * D_])[lane];

    int kreg = (lane < dn) ? g_csr_n[beg + lane] : 0;
    int ereg = (lane < dn) ? g_kept_e[kreg] : 0;

    float m = -INFINITY;
    int dn32 = dn < 32 ? dn : 32;
    for (int j = 0; j < dn32; j++) {
        int k = __shfl_sync(0xffffffffu, kreg, j);
        int e = __shfl_sync(0xffffffffu, ereg, j);
        float4 ev = ((const float4*)&g_edge4[(size_t)e * D_])[lane];
        float s = xv.x*ev.x + xv.y*ev.y + xv.z*ev.z + xv.w*ev.w;
#pragma unroll
        for (int o = 16; o; o >>= 1) s += __shfl_xor_sync(0xffffffffu, s, o);
        s *= INV_TEMP;
        if (lane == 0) g_score[k] = s;
        m = fmaxf(m, s);
    }
    for (int j = 32; j < dn; j++) {
        int k = g_csr_n[beg + j];
        float4 ev = ((const float4*)&g_edge4[(size_t)g_kept_e[k] * D_])[lane];
        float s = xv.x*ev.x + xv.y*ev.y + xv.z*ev.z + xv.w*ev.w;
#pragma unroll
        for (int o = 16; o; o >>= 1) s += __shfl_xor_sync(0xffffffffu, s, o);
        s *= INV_TEMP;
        if (lane == 0) g_score[k] = s;
        m = fmaxf(m, s);
    }
    float z = 0.f;
    for (int j = lane; j < dn; j += 32) z += expf(g_score[g_csr_n[beg + j]] - m);
#pragma unroll
    for (int o = 16; o; o >>= 1) z += __shfl_xor_sync(0xffffffffu, z, o);
    float invz = (dn > 0) ? (1.0f / z) : 0.f;
    for (int j = lane; j < dn; j += 32) {
        int k = g_csr_n[beg + j];
        g_Qval[k] = EM1 * g + expf(g_score[k] - m) * invz;
    }
    if (lane == 0) {
        g_w[n] = w;
        g_r[n] = (dn > 0) ? ((float)dn * EM1 * g + 1.0f) : 0.0f;
    }
}

__global__ void k_y2r() {
    if (blockIdx.x < N_EDGES) {
        int e = blockIdx.x, tid = threadIdx.x, lane = tid & 31, wg = tid >> 5;
        int beg = g_rowptr_e[e], end = g_rowptr_e[e + 1];
        int deg = end - beg;
        __shared__ int   sn[MAXDEG];
        __shared__ float sq[MAXDEG];
        __shared__ float sacc[4][D_];
        for (int j = tid; j < deg; j += 128) {
            int k = g_csr_e[beg + j];
            sn[j] = g_kept_n[k];
            sq[j] = g_Qval[k];
        }
        __syncthreads();
        float4 a = make_float4(0.f,0.f,0.f,0.f);
        for (int j = wg; j < deg; j += 4) {
            float4 v = ((const float4*)&g_x4[(size_t)sn[j] * D_])[lane];
            float q = sq[j];
            a.x = fmaf(q, v.x, a.x); a.y = fmaf(q, v.y, a.y);
            a.z = fmaf(q, v.z, a.z); a.w = fmaf(q, v.w, a.w);
        }
        ((float4*)&sacc[wg][0])[lane] = a;
        __syncthreads();
        int d = tid;
        g_Y2[(size_t)e * D_ + d] = sacc[0][d] + sacc[1][d] + sacc[2][d] + sacc[3][d];
    } else {
        int d = threadIdx.x;
        int r0 = (blockIdx.x - N_EDGES) * 128;
        float t = 0.f, p1 = 0.f, p2 = 0.f;
        for (int r = 0; r < 128; r++) {
            int n = r0 + r;
            float x = g_x4[(size_t)n * D_ + d];
            t  = fmaf(g_v[n], x, t);
            p1 = fmaf(g_w[n], x, p1);
            p2 = fmaf(g_r[n], x, p2);
        }
        atomicAdd(&g_t[d], t);
        atomicAdd(&g_p1[d], p1);
        atomicAdd(&g_p2[d], p2);
    }
}

__global__ void k_final(float* __restrict__ out) {
    int n = blockIdx.x, tid = threadIdx.x, lane = tid & 31, wg = tid >> 5;
    int beg = g_rowptr_n[n], end = g_rowptr_n[n + 1];
    int dn = end - beg;
    __shared__ int   se[MAXDEG];
    __shared__ float spv[MAXDEG];
    __shared__ float sqv[MAXDEG];
    __shared__ float sz1[4][D_];
    __shared__ float sz2[4][D_];
    for (int j = tid; j < dn; j += 128) {
        int k = g_csr_n[beg + j];
        se[j]  = g_kept_e[k];
        spv[j] = g_Pval[k];
        sqv[j] = g_Qval[k];
    }
    __syncthreads();
    float4 a1 = make_float4(0.f,0.f,0.f,0.f);
    float4 a2 = make_float4(0.f,0.f,0.f,0.f);
    for (int j = wg; j < dn; j += 4) {
        size_t roff = (size_t)se[j] * D_;
        float4 v1 = ((const float4*)&g_Y [roff])[lane];
        float4 v2 = ((const float4*)&g_Y2[roff])[lane];
        float p = spv[j], q = sqv[j];
        a1.x = fmaf(p, v1.x, a1.x); a1.y = fmaf(p, v1.y, a1.y);
        a1.z = fmaf(p, v1.z, a1.z); a1.w = fmaf(p, v1.w, a1.w);
        a2.x = fmaf(q, v2.x, a2.x); a2.y = fmaf(q, v2.y, a2.y);
        a2.z = fmaf(q, v2.z, a2.z); a2.w = fmaf(q, v2.w, a2.w);
    }
    ((float4*)&sz1[wg][0])[lane] = a1;
    ((float4*)&sz2[wg][0])[lane] = a2;
    __syncthreads();
    int d = tid;
    float z1 = sz1[0][d] + sz1[1][d] + sz1[2][d] + sz1[3][d];
    float z2 = sz2[0][d] + sz2[1][d] + sz2[2][d] + sz2[3][d];
    float val = (g_alpha + g_v[n]) * g_s[d] + g_t[d]
              + ((float)N_EDGES * g_w[n] + g_r[n]) * g_p1[d]
              + g_w[n] * g_p2[d] + z1 + z2;
    out[(size_t)n * D_ + d] = (val > 0.f) ? val : expm1f(val);
}

// ---------------- launch ----------------
extern "C" void kernel_launch(void* const* d_in, const int* in_sizes, int n_in,
                              void* d_out, int out_size) {
    const float* x      = (const float*)d_in[0];
    const float* W      = (const float*)d_in[1];
    const float* W2     = (const float*)d_in[2];
    const float* W3     = (const float*)d_in[3];
    const float* bias   = (const float*)d_in[4];
    const float* q_ctx  = (const float*)d_in[5];
    const int*   hidx   = (const int*)d_in[6];
    const int* nodes = hidx;
    const int* edges = hidx + NNZ_IN;
    float* out = (float*)d_out;

    // persistent side stream + events for capture fork/join (created once;
    // identical launch sequence every call — deterministic work)
    static cudaStream_t s_side = nullptr;
    static cudaEvent_t  ev_fork = nullptr, ev_join = nullptr;
    if (s_side == nullptr) {
        cudaStreamCreateWithFlags(&s_side, cudaStreamNonBlocking);
        cudaEventCreateWithFlags(&ev_fork, cudaEventDisableTiming);
        cudaEventCreateWithFlags(&ev_join, cudaEventDisableTiming);
    }

    k_zero<<<1024, 256>>>();

    // fork: index plumbing on side stream, GEMM on main stream
    cudaEventRecord(ev_fork, 0);
    cudaStreamWaitEvent(s_side, ev_fork, 0);

    k_dedup<<<NNZ_IN / 256, 256, 0, s_side>>>(nodes, edges);
    k_scan2<<<2, 1024, 0, s_side>>>();
    k_fill<<<2 * NNZ_IN / 256, 256, 0, s_side>>>();
    cudaEventRecord(ev_join, s_side);

    k_gemm_x<<<N_NODES / 32, 512>>>(x, W, W2, bias, q_ctx);

    // join
    cudaStreamWaitEvent(0, ev_join, 0);

    k_edge<<<N_EDGES, 128>>>();
    k_gemm_e4<<<N_EDGES / 16, 256>>>(W3);
    k_node2f<<<N_NODES / 8, 256>>>();
    k_y2r<<<N_EDGES + N_NODES / 128, 128>>>();
    k_final<<<N_NODES, 128>>>(out);
}